// round 9
// baseline (speedup 1.0000x reference)
#include <cuda_runtime.h>
#include <math.h>

#define DIMX 1024
#define NH   16
#define HD   64
#define DFF  4096
#define BB   2
#define SSQ  2048
#define MTOT (BB*SSQ)
#define EPSV 1e-6f

// ---------------- scratch (device globals) ----------------------------------
__device__ __align__(256) float g_h   [MTOT*DIMX];
__device__ __align__(256) float g_q   [MTOT*DIMX];
__device__ __align__(256) float g_k   [MTOT*DIMX];
__device__ __align__(256) float g_v   [MTOT*DIMX];
__device__ __align__(256) float g_attn[MTOT*DIMX];
__device__ __align__(256) float g_x2  [MTOT*DIMX];
__device__ __align__(256) float g_ffh [MTOT*DFF];
__device__ __align__(256) float g_wc  [4*DIMX*DIMX + 2*DIMX*DFF];   // tf32 weights

// ---------------- helpers ----------------------------------------------------
__device__ __forceinline__ unsigned f2tf(float f) {
    unsigned u;
    asm("cvt.rna.tf32.f32 %0, %1;" : "=r"(u) : "f"(f));
    return u;
}
__device__ __forceinline__ void cp16(unsigned s, const void* g) {
    asm volatile("cp.async.cg.shared.global [%0], [%1], 16;" :: "r"(s), "l"(g));
}
#define CP_COMMIT() asm volatile("cp.async.commit_group;")
#define CP_WAIT(n)  asm volatile("cp.async.wait_group %0;" :: "n"(n))

#define MMA_TF32(c, a, b) asm volatile( \
    "mma.sync.aligned.m16n8k8.row.col.f32.tf32.tf32.f32 " \
    "{%0,%1,%2,%3}, {%4,%5,%6,%7}, {%8,%9}, {%0,%1,%2,%3};" \
    : "+f"((c)[0]), "+f"((c)[1]), "+f"((c)[2]), "+f"((c)[3]) \
    : "r"((a)[0]), "r"((a)[1]), "r"((a)[2]), "r"((a)[3]), \
      "r"((b)[0]), "r"((b)[1]))

// ---------------- single-launch weight convert (all 6 weights) ----------------
#define W1 (DIMX*DIMX/4)
#define W2 (DIMX*DFF/4)
#define WTOT (4*W1 + 2*W2)

__global__ void __launch_bounds__(256) prep_all(
    const float* __restrict__ wq, const float* __restrict__ wk,
    const float* __restrict__ wv, const float* __restrict__ wo,
    const float* __restrict__ wu, const float* __restrict__ wd,
    float* __restrict__ dst)
{
    int i = blockIdx.x * 256 + threadIdx.x;
    if (i >= WTOT) return;
    const float* src;
    int off;
    if      (i < 1*W1) { src = wq; off = i; }
    else if (i < 2*W1) { src = wk; off = i - 1*W1; }
    else if (i < 3*W1) { src = wv; off = i - 2*W1; }
    else if (i < 4*W1) { src = wo; off = i - 3*W1; }
    else if (i < 4*W1 + W2) { src = wu; off = i - 4*W1; }
    else               { src = wd; off = i - 4*W1 - W2; }
    float4 v = reinterpret_cast<const float4*>(src)[off];
    uint4 u;
    u.x = f2tf(v.x); u.y = f2tf(v.y); u.z = f2tf(v.z); u.w = f2tf(v.w);
    reinterpret_cast<uint4*>(dst)[i] = u;
}

// ---------------- LayerNorm (emits tf32-rounded output) -----------------------
__global__ void __launch_bounds__(256) ln_kernel(
    const float* __restrict__ x, const float* __restrict__ alpha,
    const float* __restrict__ beta, float* __restrict__ y)
{
    int row = blockIdx.x;
    int t = threadIdx.x;
    const float4* xr = reinterpret_cast<const float4*>(x + (size_t)row * DIMX);
    float4 v = xr[t];
    float s  = v.x + v.y + v.z + v.w;
    float sq = v.x*v.x + v.y*v.y + v.z*v.z + v.w*v.w;
    #pragma unroll
    for (int o = 16; o; o >>= 1) {
        s  += __shfl_xor_sync(0xffffffffu, s,  o);
        sq += __shfl_xor_sync(0xffffffffu, sq, o);
    }
    __shared__ float ss[8], ssq[8];
    int w = t >> 5, l = t & 31;
    if (l == 0) { ss[w] = s; ssq[w] = sq; }
    __syncthreads();
    if (w == 0) {
        s  = (l < 8) ? ss[l]  : 0.f;
        sq = (l < 8) ? ssq[l] : 0.f;
        #pragma unroll
        for (int o = 4; o; o >>= 1) {
            s  += __shfl_xor_sync(0xffffffffu, s,  o);
            sq += __shfl_xor_sync(0xffffffffu, sq, o);
        }
        if (l == 0) { ss[0] = s; ssq[0] = sq; }
    }
    __syncthreads();
    s = ss[0]; sq = ssq[0];
    float mu  = s * (1.0f / DIMX);
    float var = (sq - (float)DIMX * mu * mu) * (1.0f / (DIMX - 1));
    float sig = sqrtf(fmaxf(var, 0.f));
    float inv = 1.0f / (sig + EPSV);
    float4 a = reinterpret_cast<const float4*>(alpha)[t];
    float4 b = reinterpret_cast<const float4*>(beta)[t];
    uint4 o4;
    o4.x = f2tf(a.x * (v.x - mu) * inv + b.x);
    o4.y = f2tf(a.y * (v.y - mu) * inv + b.y);
    o4.z = f2tf(a.z * (v.z - mu) * inv + b.z);
    o4.w = f2tf(a.w * (v.w - mu) * inv + b.w);
    reinterpret_cast<uint4*>(y + (size_t)row * DIMX)[t] = o4;
}

// ---------------- TF32 tensor GEMM: 512 thr, 32x32 warp tiles, 2 CTA/SM -------
// C[M,N] = A[M,K] @ B[K,N]. 128x128x32 CTA tile, 16 warps in 4x4 grid,
// 3-stage cp.async. Low regs (<=64) -> 32 warps/SM.
#define STAGES 3
#define GPA 36
#define GPB 136
#define STAGE_U32 (128*GPA + 32*GPB)
#define GEMM_SMEM (STAGES * STAGE_U32 * 4)

template<bool BIAS, bool RELU, bool RES, bool CVTOUT>
__global__ void __launch_bounds__(512, 2) gemm_tc(
    const float* __restrict__ A, const float* __restrict__ B,
    const float* __restrict__ bias, const float* __restrict__ res,
    float* __restrict__ C, int M, int N, int K)
{
    extern __shared__ unsigned smg[];
    const int tid  = threadIdx.x;
    const int bm   = blockIdx.y * 128, bn = blockIdx.x * 128;
    const int warp = tid >> 5, lane = tid & 31;
    const int wm   = (warp >> 2) << 5;      // 0,32,64,96
    const int wn   = (warp & 3) << 5;       // 0,32,64,96
    const int g    = lane >> 2, q = lane & 3;

    const int arow = tid >> 3, acol = (tid & 7) << 2;   // A: 64 rows/pass x2
    const int brow = tid >> 5, bcol = (tid & 31) << 2;  // B: 16 rows/pass x2

    const float* Ag = A + (size_t)(bm + arow) * K + acol;
    const float* Bg = B + (size_t)brow * N + bn + bcol;
    const unsigned sbase = (unsigned)__cvta_generic_to_shared(smg);

    float acc[2][4][4];
    #pragma unroll
    for (int mi = 0; mi < 2; mi++)
        #pragma unroll
        for (int nj = 0; nj < 4; nj++)
            #pragma unroll
            for (int e = 0; e < 4; e++) acc[mi][nj][e] = 0.f;

    const int nt = K >> 5;

    #define G_ISSUE(buf, kt) do { \
        unsigned ab_ = sbase + (buf) * (STAGE_U32 * 4); \
        unsigned bb_ = ab_ + 128 * GPA * 4; \
        const float* Ap_ = Ag + (kt) * 32; \
        const float* Bp_ = Bg + (size_t)(kt) * 32 * N; \
        _Pragma("unroll") \
        for (int i_ = 0; i_ < 2; i_++) { \
            cp16(ab_ + ((arow + 64 * i_) * GPA + acol) * 4, Ap_ + (size_t)(64 * i_) * K); \
            cp16(bb_ + ((brow + 16 * i_) * GPB + bcol) * 4, Bp_ + (size_t)(16 * i_) * N); \
        } \
    } while (0)

    #pragma unroll
    for (int s = 0; s < STAGES - 1; s++) {
        if (s < nt) G_ISSUE(s, s);
        CP_COMMIT();
    }

    for (int kt = 0; kt < nt; kt++) {
        CP_WAIT(STAGES - 2);
        __syncthreads();
        int nl = kt + STAGES - 1;
        if (nl < nt) G_ISSUE(nl % STAGES, nl);
        CP_COMMIT();

        const unsigned* Ab = smg + (kt % STAGES) * STAGE_U32;
        const unsigned* Bb = Ab + 128 * GPA;
        #pragma unroll
        for (int ks = 0; ks < 4; ks++) {
            const int kk = ks << 3;
            unsigned af[2][4], bf[4][2];
            #pragma unroll
            for (int mi = 0; mi < 2; mi++) {
                int r = wm + (mi << 4) + g;
                af[mi][0] = Ab[r * GPA + kk + q];
                af[mi][1] = Ab[(r + 8) * GPA + kk + q];
                af[mi][2] = Ab[r * GPA + kk + q + 4];
                af[mi][3] = Ab[(r + 8) * GPA + kk + q + 4];
            }
            #pragma unroll
            for (int nj = 0; nj < 4; nj++) {
                int c = wn + (nj << 3) + g;
                bf[nj][0] = Bb[(kk + q) * GPB + c];
                bf[nj][1] = Bb[(kk + q + 4) * GPB + c];
            }
            #pragma unroll
            for (int mi = 0; mi < 2; mi++)
                #pragma unroll
                for (int nj = 0; nj < 4; nj++)
                    MMA_TF32(acc[mi][nj], af[mi], bf[nj]);
        }
    }

    // epilogue
    #pragma unroll
    for (int mi = 0; mi < 2; mi++) {
        int r = bm + wm + (mi << 4) + g;
        #pragma unroll
        for (int nj = 0; nj < 4; nj++) {
            int c = bn + wn + (nj << 3) + (q << 1);
            float2 v0, v1;
            v0.x = acc[mi][nj][0]; v0.y = acc[mi][nj][1];
            v1.x = acc[mi][nj][2]; v1.y = acc[mi][nj][3];
            if (BIAS) {
                float2 bv = *reinterpret_cast<const float2*>(bias + c);
                v0.x += bv.x; v0.y += bv.y; v1.x += bv.x; v1.y += bv.y;
            }
            if (RELU) {
                v0.x = fmaxf(v0.x, 0.f); v0.y = fmaxf(v0.y, 0.f);
                v1.x = fmaxf(v1.x, 0.f); v1.y = fmaxf(v1.y, 0.f);
            }
            if (RES) {
                float2 r0 = *reinterpret_cast<const float2*>(res + (size_t)r * N + c);
                float2 r1 = *reinterpret_cast<const float2*>(res + (size_t)(r + 8) * N + c);
                v0.x += r0.x; v0.y += r0.y; v1.x += r1.x; v1.y += r1.y;
            }
            if (CVTOUT) {
                v0.x = __uint_as_float(f2tf(v0.x)); v0.y = __uint_as_float(f2tf(v0.y));
                v1.x = __uint_as_float(f2tf(v1.x)); v1.y = __uint_as_float(f2tf(v1.y));
            }
            *reinterpret_cast<float2*>(C + (size_t)r * N + c) = v0;
            *reinterpret_cast<float2*>(C + (size_t)(r + 8) * N + c) = v1;
        }
    }
}

// ---------------- TF32 flash attention (round-3/8 config, unchanged) ----------
#define AQS 68
#define AKS 68
#define AVS 72
#define APS 68
#define ATT_SMEM ((128*AQS + 2*64*AKS + 2*64*AVS) * 4)

__global__ void __launch_bounds__(256, 2) attn_tc(
    const float* __restrict__ qg, const float* __restrict__ kg,
    const float* __restrict__ vg, float* __restrict__ og)
{
    extern __shared__ unsigned sma[];
    unsigned* Qs = sma;
    unsigned* Ks = Qs + 128 * AQS;
    unsigned* Vs = Ks + 2 * 64 * AKS;
    unsigned* Ps = Qs;                    // alias

    const int tid  = threadIdx.x;
    const int warp = tid >> 5, lane = tid & 31;
    const int g    = lane >> 2, q4 = lane & 3;
    const int bh   = blockIdx.y;
    const int b    = bh >> 4, h = bh & 15;
    const int q0   = blockIdx.x * 128;
    const size_t base = ((size_t)b * SSQ) * DIMX + h * HD;
    const int r0 = warp << 4;
    const unsigned sbase = (unsigned)__cvta_generic_to_shared(sma);
    const unsigned ksb = sbase + 128 * AQS * 4;
    const unsigned vsb = ksb + 2 * 64 * AKS * 4;

    #pragma unroll
    for (int i = 0; i < 8; i++) {
        int f = tid + (i << 8);
        int row = f >> 4;
        int d4 = (f & 15) << 2;
        cp16(sbase + (row * AQS + d4) * 4, qg + base + (size_t)(q0 + row) * DIMX + d4);
    }
    CP_COMMIT();

    #define A_ISSUE(buf, kt) do { \
        _Pragma("unroll") \
        for (int i_ = 0; i_ < 4; i_++) { \
            int f_ = tid + (i_ << 8); \
            int key_ = f_ >> 4; \
            int d4_ = (f_ & 15) << 2; \
            size_t go_ = base + (size_t)((kt) + key_) * DIMX + d4_; \
            cp16(ksb + ((buf) * 64 * AKS + key_ * AKS + d4_) * 4, kg + go_); \
            cp16(vsb + ((buf) * 64 * AVS + key_ * AVS + d4_) * 4, vg + go_); \
        } \
    } while (0)

    CP_WAIT(0);
    __syncthreads();
    unsigned aq[8][4];
    #pragma unroll
    for (int ks = 0; ks < 8; ks++) {
        int kk = ks << 3;
        aq[ks][0] = Qs[(r0 + g) * AQS + kk + q4];
        aq[ks][1] = Qs[(r0 + 8 + g) * AQS + kk + q4];
        aq[ks][2] = Qs[(r0 + g) * AQS + kk + q4 + 4];
        aq[ks][3] = Qs[(r0 + 8 + g) * AQS + kk + q4 + 4];
    }

    A_ISSUE(0, 0);
    CP_COMMIT();

    float m0 = -1e30f, m1 = -1e30f, l0 = 0.f, l1 = 0.f;
    float oacc[8][4];
    #pragma unroll
    for (int j = 0; j < 8; j++)
        #pragma unroll
        for (int e = 0; e < 4; e++) oacc[j][e] = 0.f;

    const int NKT = SSQ / 64;
    for (int t = 0; t < NKT; t++) {
        __syncthreads();
        if (t + 1 < NKT) A_ISSUE((t + 1) & 1, (t + 1) * 64);
        CP_COMMIT();
        CP_WAIT(1);
        __syncthreads();

        const unsigned* Kb = Ks + (t & 1) * 64 * AKS;
        const unsigned* Vb = Vs + (t & 1) * 64 * AVS;

        float s[8][4];
        #pragma unroll
        for (int j = 0; j < 8; j++)
            #pragma unroll
            for (int e = 0; e < 4; e++) s[j][e] = 0.f;
        #pragma unroll
        for (int ks = 0; ks < 8; ks++) {
            int kk = ks << 3;
            #pragma unroll
            for (int j = 0; j < 8; j++) {
                unsigned bfr[2];
                bfr[0] = Kb[((j << 3) + g) * AKS + kk + q4];
                bfr[1] = Kb[((j << 3) + g) * AKS + kk + q4 + 4];
                MMA_TF32(s[j], aq[ks], bfr);
            }
        }

        float mt0 = -1e30f, mt1 = -1e30f;
        #pragma unroll
        for (int j = 0; j < 8; j++) {
            s[j][0] *= 0.125f; s[j][1] *= 0.125f; s[j][2] *= 0.125f; s[j][3] *= 0.125f;
            mt0 = fmaxf(mt0, fmaxf(s[j][0], s[j][1]));
            mt1 = fmaxf(mt1, fmaxf(s[j][2], s[j][3]));
        }
        mt0 = fmaxf(mt0, __shfl_xor_sync(0xffffffffu, mt0, 1));
        mt0 = fmaxf(mt0, __shfl_xor_sync(0xffffffffu, mt0, 2));
        mt1 = fmaxf(mt1, __shfl_xor_sync(0xffffffffu, mt1, 1));
        mt1 = fmaxf(mt1, __shfl_xor_sync(0xffffffffu, mt1, 2));
        float mn0 = fmaxf(m0, mt0), mn1 = fmaxf(m1, mt1);
        float corr0 = __expf(m0 - mn0), corr1 = __expf(m1 - mn1);
        m0 = mn0; m1 = mn1;
        float ls0 = 0.f, ls1 = 0.f;
        #pragma unroll
        for (int j = 0; j < 8; j++) {
            float p0 = __expf(s[j][0] - mn0);
            float p1 = __expf(s[j][1] - mn0);
            float p2 = __expf(s[j][2] - mn1);
            float p3 = __expf(s[j][3] - mn1);
            ls0 += p0 + p1; ls1 += p2 + p3;
            uint2 u0; u0.x = f2tf(p0); u0.y = f2tf(p1);
            uint2 u1; u1.x = f2tf(p2); u1.y = f2tf(p3);
            *reinterpret_cast<uint2*>(Ps + (r0 + g) * APS + (j << 3) + (q4 << 1)) = u0;
            *reinterpret_cast<uint2*>(Ps + (r0 + 8 + g) * APS + (j << 3) + (q4 << 1)) = u1;
        }
        ls0 += __shfl_xor_sync(0xffffffffu, ls0, 1);
        ls0 += __shfl_xor_sync(0xffffffffu, ls0, 2);
        ls1 += __shfl_xor_sync(0xffffffffu, ls1, 1);
        ls1 += __shfl_xor_sync(0xffffffffu, ls1, 2);
        l0 = l0 * corr0 + ls0;
        l1 = l1 * corr1 + ls1;
        #pragma unroll
        for (int j = 0; j < 8; j++) {
            oacc[j][0] *= corr0; oacc[j][1] *= corr0;
            oacc[j][2] *= corr1; oacc[j][3] *= corr1;
        }
        __syncwarp();

        #pragma unroll
        for (int ks = 0; ks < 8; ks++) {
            int kk = ks << 3;
            unsigned ap[4];
            ap[0] = Ps[(r0 + g) * APS + kk + q4];
            ap[1] = Ps[(r0 + 8 + g) * APS + kk + q4];
            ap[2] = Ps[(r0 + g) * APS + kk + q4 + 4];
            ap[3] = Ps[(r0 + 8 + g) * APS + kk + q4 + 4];
            #pragma unroll
            for (int j = 0; j < 8; j++) {
                unsigned bfr[2];
                bfr[0] = Vb[(kk + q4) * AVS + (j << 3) + g];
                bfr[1] = Vb[(kk + q4 + 4) * AVS + (j << 3) + g];
                MMA_TF32(oacc[j], ap, bfr);
            }
        }
    }

    float il0 = 1.0f / l0, il1 = 1.0f / l1;
    #pragma unroll
    for (int j = 0; j < 8; j++) {
        uint2 v0, v1;
        v0.x = f2tf(oacc[j][0] * il0); v0.y = f2tf(oacc[j][1] * il0);
        v1.x = f2tf(oacc[j][2] * il1); v1.y = f2tf(oacc[j][3] * il1);
        size_t o0 = base + (size_t)(q0 + r0 + g) * DIMX + (j << 3) + (q4 << 1);
        size_t o1 = base + (size_t)(q0 + r0 + 8 + g) * DIMX + (j << 3) + (q4 << 1);
        *reinterpret_cast<uint2*>(og + o0) = v0;
        *reinterpret_cast<uint2*>(og + o1) = v1;
    }
}

// ---------------- launch ------------------------------------------------------
extern "C" void kernel_launch(void* const* d_in, const int* in_sizes, int n_in,
                              void* d_out, int out_size)
{
    const float* x    = (const float*)d_in[0];
    const float* wq   = (const float*)d_in[2];
    const float* wk   = (const float*)d_in[3];
    const float* wv   = (const float*)d_in[4];
    const float* wo   = (const float*)d_in[5];
    const float* w_up = (const float*)d_in[6];
    const float* b_up = (const float*)d_in[7];
    const float* w_dn = (const float*)d_in[8];
    const float* b_dn = (const float*)d_in[9];
    const float* l1a  = (const float*)d_in[10];
    const float* l1b  = (const float*)d_in[11];
    const float* l2a  = (const float*)d_in[12];
    const float* l2b  = (const float*)d_in[13];
    float* out = (float*)d_out;

    float *h, *qb, *kb, *vb, *attn, *x2, *ffh, *wc;
    cudaGetSymbolAddress((void**)&h,    g_h);
    cudaGetSymbolAddress((void**)&qb,   g_q);
    cudaGetSymbolAddress((void**)&kb,   g_k);
    cudaGetSymbolAddress((void**)&vb,   g_v);
    cudaGetSymbolAddress((void**)&attn, g_attn);
    cudaGetSymbolAddress((void**)&x2,   g_x2);
    cudaGetSymbolAddress((void**)&ffh,  g_ffh);
    cudaGetSymbolAddress((void**)&wc,   g_wc);

    float* wq_c = wc;
    float* wk_c = wc + 1 * DIMX * DIMX;
    float* wv_c = wc + 2 * DIMX * DIMX;
    float* wo_c = wc + 3 * DIMX * DIMX;
    float* wu_c = wc + 4 * DIMX * DIMX;
    float* wd_c = wu_c + DIMX * DFF;

    cudaFuncSetAttribute(gemm_tc<false,false,false,true >, cudaFuncAttributeMaxDynamicSharedMemorySize, GEMM_SMEM);
    cudaFuncSetAttribute(gemm_tc<false,false,true ,false>, cudaFuncAttributeMaxDynamicSharedMemorySize, GEMM_SMEM);
    cudaFuncSetAttribute(gemm_tc<true ,true ,false,true >, cudaFuncAttributeMaxDynamicSharedMemorySize, GEMM_SMEM);
    cudaFuncSetAttribute(gemm_tc<true ,false,true ,false>, cudaFuncAttributeMaxDynamicSharedMemorySize, GEMM_SMEM);
    cudaFuncSetAttribute(attn_tc, cudaFuncAttributeMaxDynamicSharedMemorySize, ATT_SMEM);

    dim3 thr(256), thr5(512);

    // 0: single weight-convert launch
    prep_all<<<(WTOT + 255) / 256, thr>>>(wq, wk, wv, wo, w_up, w_dn, wc);

    // 1: h = LN1(x)  (tf32)
    ln_kernel<<<MTOT, thr>>>(x, l1a, l1b, h);

    // 2,3,4: QKV projections (tf32 out)
    gemm_tc<false,false,false,true><<<dim3(DIMX/128, MTOT/128), thr5, GEMM_SMEM>>>(h, wq_c, nullptr, nullptr, qb, MTOT, DIMX, DIMX);
    gemm_tc<false,false,false,true><<<dim3(DIMX/128, MTOT/128), thr5, GEMM_SMEM>>>(h, wk_c, nullptr, nullptr, kb, MTOT, DIMX, DIMX);
    gemm_tc<false,false,false,true><<<dim3(DIMX/128, MTOT/128), thr5, GEMM_SMEM>>>(h, wv_c, nullptr, nullptr, vb, MTOT, DIMX, DIMX);

    // 5: attention (tf32 out)
    attn_tc<<<dim3(SSQ/128, BB*NH), thr, ATT_SMEM>>>(qb, kb, vb, attn);

    // 6: x2 = x + attn @ wo
    gemm_tc<false,false,true,false><<<dim3(DIMX/128, MTOT/128), thr5, GEMM_SMEM>>>(attn, wo_c, nullptr, x, x2, MTOT, DIMX, DIMX);

    // 7: h = LN2(x2)
    ln_kernel<<<MTOT, thr>>>(x2, l2a, l2b, h);

    // 8: ffh = relu(h @ w_up + b_up)  (tf32 out)
    gemm_tc<true,true,false,true><<<dim3(DFF/128, MTOT/128), thr5, GEMM_SMEM>>>(h, wu_c, b_up, nullptr, ffh, MTOT, DFF, DIMX);

    // 9: out = x2 + ffh @ w_down + b_down
    gemm_tc<true,false,true,false><<<dim3(DIMX/128, MTOT/128), thr5, GEMM_SMEM>>>(ffh, wd_c, b_dn, x2, out, MTOT, DIMX, DFF);
}

// round 10
// speedup vs baseline: 1.2373x; 1.2373x over previous
#include <cuda_runtime.h>
#include <cuda_bf16.h>
#include <math.h>

#define DIMX 1024
#define NH   16
#define HD   64
#define DFF  4096
#define BB   2
#define SSQ  2048
#define MTOT (BB*SSQ)
#define EPSV 1e-6f

// ---------------- scratch (device globals) ----------------------------------
__device__ __align__(256) float g_h   [MTOT*DIMX];
__device__ __align__(256) float g_q   [MTOT*DIMX];   // used as bf16 [M][1024]
__device__ __align__(256) float g_k   [MTOT*DIMX];   // used as bf16 [M][1024]
__device__ __align__(256) float g_v   [MTOT*DIMX];   // used as bf16 vT [1024][M]
__device__ __align__(256) float g_attn[MTOT*DIMX];
__device__ __align__(256) float g_x2  [MTOT*DIMX];
__device__ __align__(256) float g_ffh [MTOT*DFF];
__device__ __align__(256) float g_wc  [4*DIMX*DIMX + 2*DIMX*DFF];   // tf32 weights

// ---------------- helpers ----------------------------------------------------
__device__ __forceinline__ unsigned f2tf(float f) {
    unsigned u;
    asm("cvt.rna.tf32.f32 %0, %1;" : "=r"(u) : "f"(f));
    return u;
}
__device__ __forceinline__ void cp16(unsigned s, const void* g) {
    asm volatile("cp.async.cg.shared.global [%0], [%1], 16;" :: "r"(s), "l"(g));
}
#define CP_COMMIT() asm volatile("cp.async.commit_group;")
#define CP_WAIT(n)  asm volatile("cp.async.wait_group %0;" :: "n"(n))

#define MMA_TF32(c, a, b) asm volatile( \
    "mma.sync.aligned.m16n8k8.row.col.f32.tf32.tf32.f32 " \
    "{%0,%1,%2,%3}, {%4,%5,%6,%7}, {%8,%9}, {%0,%1,%2,%3};" \
    : "+f"((c)[0]), "+f"((c)[1]), "+f"((c)[2]), "+f"((c)[3]) \
    : "r"((a)[0]), "r"((a)[1]), "r"((a)[2]), "r"((a)[3]), \
      "r"((b)[0]), "r"((b)[1]))

#define MMA_BF16(c, a0, a1, a2, a3, b0, b1) asm volatile( \
    "mma.sync.aligned.m16n8k16.row.col.f32.bf16.bf16.f32 " \
    "{%0,%1,%2,%3}, {%4,%5,%6,%7}, {%8,%9}, {%0,%1,%2,%3};" \
    : "+f"((c)[0]), "+f"((c)[1]), "+f"((c)[2]), "+f"((c)[3]) \
    : "r"(a0), "r"(a1), "r"(a2), "r"(a3), "r"(b0), "r"(b1))

// ---------------- single-launch weight convert --------------------------------
#define W1 (DIMX*DIMX/4)
#define W2 (DIMX*DFF/4)
#define WTOT (4*W1 + 2*W2)

__global__ void __launch_bounds__(256) prep_all(
    const float* __restrict__ wq, const float* __restrict__ wk,
    const float* __restrict__ wv, const float* __restrict__ wo,
    const float* __restrict__ wu, const float* __restrict__ wd,
    float* __restrict__ dst)
{
    int i = blockIdx.x * 256 + threadIdx.x;
    if (i >= WTOT) return;
    const float* src;
    int off;
    if      (i < 1*W1) { src = wq; off = i; }
    else if (i < 2*W1) { src = wk; off = i - 1*W1; }
    else if (i < 3*W1) { src = wv; off = i - 2*W1; }
    else if (i < 4*W1) { src = wo; off = i - 3*W1; }
    else if (i < 4*W1 + W2) { src = wu; off = i - 4*W1; }
    else               { src = wd; off = i - 4*W1 - W2; }
    float4 v = reinterpret_cast<const float4*>(src)[off];
    uint4 u;
    u.x = f2tf(v.x); u.y = f2tf(v.y); u.z = f2tf(v.z); u.w = f2tf(v.w);
    reinterpret_cast<uint4*>(dst)[i] = u;
}

// ---------------- LayerNorm (emits tf32-rounded output) -----------------------
__global__ void __launch_bounds__(256) ln_kernel(
    const float* __restrict__ x, const float* __restrict__ alpha,
    const float* __restrict__ beta, float* __restrict__ y)
{
    int row = blockIdx.x;
    int t = threadIdx.x;
    const float4* xr = reinterpret_cast<const float4*>(x + (size_t)row * DIMX);
    float4 v = xr[t];
    float s  = v.x + v.y + v.z + v.w;
    float sq = v.x*v.x + v.y*v.y + v.z*v.z + v.w*v.w;
    #pragma unroll
    for (int o = 16; o; o >>= 1) {
        s  += __shfl_xor_sync(0xffffffffu, s,  o);
        sq += __shfl_xor_sync(0xffffffffu, sq, o);
    }
    __shared__ float ss[8], ssq[8];
    int w = t >> 5, l = t & 31;
    if (l == 0) { ss[w] = s; ssq[w] = sq; }
    __syncthreads();
    if (w == 0) {
        s  = (l < 8) ? ss[l]  : 0.f;
        sq = (l < 8) ? ssq[l] : 0.f;
        #pragma unroll
        for (int o = 4; o; o >>= 1) {
            s  += __shfl_xor_sync(0xffffffffu, s,  o);
            sq += __shfl_xor_sync(0xffffffffu, sq, o);
        }
        if (l == 0) { ss[0] = s; ssq[0] = sq; }
    }
    __syncthreads();
    s = ss[0]; sq = ssq[0];
    float mu  = s * (1.0f / DIMX);
    float var = (sq - (float)DIMX * mu * mu) * (1.0f / (DIMX - 1));
    float sig = sqrtf(fmaxf(var, 0.f));
    float inv = 1.0f / (sig + EPSV);
    float4 a = reinterpret_cast<const float4*>(alpha)[t];
    float4 b = reinterpret_cast<const float4*>(beta)[t];
    uint4 o4;
    o4.x = f2tf(a.x * (v.x - mu) * inv + b.x);
    o4.y = f2tf(a.y * (v.y - mu) * inv + b.y);
    o4.z = f2tf(a.z * (v.z - mu) * inv + b.z);
    o4.w = f2tf(a.w * (v.w - mu) * inv + b.w);
    reinterpret_cast<uint4*>(y + (size_t)row * DIMX)[t] = o4;
}

// ---------------- TF32 tensor GEMM (round-8 config, OM output modes) ----------
// OM: 0 fp32, 1 tf32-rounded fp32, 2 bf16 row-major pairs, 3 bf16 transposed.
#define STAGES 3
#define GPA 36
#define GPB 136
#define STAGE_U32 (128*GPA + 32*GPB)
#define GEMM_SMEM (STAGES * STAGE_U32 * 4)

template<int OM, bool BIAS, bool RELU, bool RES>
__global__ void __launch_bounds__(256, 2) gemm_tc(
    const float* __restrict__ A, const float* __restrict__ B,
    const float* __restrict__ bias, const float* __restrict__ res,
    float* __restrict__ C, __nv_bfloat16* __restrict__ Cb,
    int M, int N, int K)
{
    extern __shared__ unsigned smg[];
    const int tid  = threadIdx.x;
    const int bm   = blockIdx.y * 128, bn = blockIdx.x * 128;
    const int warp = tid >> 5, lane = tid & 31;
    const int wm   = (warp >> 2) << 6;
    const int wn   = (warp & 3) << 5;
    const int g    = lane >> 2, q = lane & 3;

    const int arow = tid >> 3, acol = (tid & 7) << 2;
    const int brow = tid >> 5, bcol = (tid & 31) << 2;

    const float* Ag = A + (size_t)(bm + arow) * K + acol;
    const float* Bg = B + (size_t)brow * N + bn + bcol;
    const unsigned sbase = (unsigned)__cvta_generic_to_shared(smg);

    float acc[4][4][4];
    #pragma unroll
    for (int mi = 0; mi < 4; mi++)
        #pragma unroll
        for (int nj = 0; nj < 4; nj++)
            #pragma unroll
            for (int e = 0; e < 4; e++) acc[mi][nj][e] = 0.f;

    const int nt = K >> 5;

    #define G_ISSUE(buf, kt) do { \
        unsigned ab_ = sbase + (buf) * (STAGE_U32 * 4); \
        unsigned bb_ = ab_ + 128 * GPA * 4; \
        const float* Ap_ = Ag + (kt) * 32; \
        const float* Bp_ = Bg + (size_t)(kt) * 32 * N; \
        _Pragma("unroll") \
        for (int i_ = 0; i_ < 4; i_++) { \
            cp16(ab_ + ((arow + 32 * i_) * GPA + acol) * 4, Ap_ + (size_t)(32 * i_) * K); \
            cp16(bb_ + ((brow + 8 * i_) * GPB + bcol) * 4, Bp_ + (size_t)(8 * i_) * N); \
        } \
    } while (0)

    #pragma unroll
    for (int s = 0; s < STAGES - 1; s++) {
        if (s < nt) G_ISSUE(s, s);
        CP_COMMIT();
    }

    for (int kt = 0; kt < nt; kt++) {
        CP_WAIT(STAGES - 2);
        __syncthreads();
        int nl = kt + STAGES - 1;
        if (nl < nt) G_ISSUE(nl % STAGES, nl);
        CP_COMMIT();

        const unsigned* Ab = smg + (kt % STAGES) * STAGE_U32;
        const unsigned* Bb = Ab + 128 * GPA;
        #pragma unroll
        for (int ks = 0; ks < 4; ks++) {
            const int kk = ks << 3;
            unsigned af[4][4], bf[4][2];
            #pragma unroll
            for (int mi = 0; mi < 4; mi++) {
                int r = wm + (mi << 4) + g;
                af[mi][0] = Ab[r * GPA + kk + q];
                af[mi][1] = Ab[(r + 8) * GPA + kk + q];
                af[mi][2] = Ab[r * GPA + kk + q + 4];
                af[mi][3] = Ab[(r + 8) * GPA + kk + q + 4];
            }
            #pragma unroll
            for (int nj = 0; nj < 4; nj++) {
                int c = wn + (nj << 3) + g;
                bf[nj][0] = Bb[(kk + q) * GPB + c];
                bf[nj][1] = Bb[(kk + q + 4) * GPB + c];
            }
            #pragma unroll
            for (int mi = 0; mi < 4; mi++)
                #pragma unroll
                for (int nj = 0; nj < 4; nj++)
                    MMA_TF32(acc[mi][nj], af[mi], bf[nj]);
        }
    }

    // epilogue
    #pragma unroll
    for (int mi = 0; mi < 4; mi++) {
        int r = bm + wm + (mi << 4) + g;
        #pragma unroll
        for (int nj = 0; nj < 4; nj++) {
            int c = bn + wn + (nj << 3) + (q << 1);
            float2 v0, v1;
            v0.x = acc[mi][nj][0]; v0.y = acc[mi][nj][1];
            v1.x = acc[mi][nj][2]; v1.y = acc[mi][nj][3];
            if (BIAS) {
                float2 bv = *reinterpret_cast<const float2*>(bias + c);
                v0.x += bv.x; v0.y += bv.y; v1.x += bv.x; v1.y += bv.y;
            }
            if (RELU) {
                v0.x = fmaxf(v0.x, 0.f); v0.y = fmaxf(v0.y, 0.f);
                v1.x = fmaxf(v1.x, 0.f); v1.y = fmaxf(v1.y, 0.f);
            }
            if (RES) {
                float2 r0 = *reinterpret_cast<const float2*>(res + (size_t)r * N + c);
                float2 r1 = *reinterpret_cast<const float2*>(res + (size_t)(r + 8) * N + c);
                v0.x += r0.x; v0.y += r0.y; v1.x += r1.x; v1.y += r1.y;
            }
            if (OM == 0 || OM == 1) {
                if (OM == 1) {
                    v0.x = __uint_as_float(f2tf(v0.x)); v0.y = __uint_as_float(f2tf(v0.y));
                    v1.x = __uint_as_float(f2tf(v1.x)); v1.y = __uint_as_float(f2tf(v1.y));
                }
                *reinterpret_cast<float2*>(C + (size_t)r * N + c) = v0;
                *reinterpret_cast<float2*>(C + (size_t)(r + 8) * N + c) = v1;
            } else if (OM == 2) {
                __nv_bfloat162 p0 = __floats2bfloat162_rn(v0.x, v0.y);
                __nv_bfloat162 p1 = __floats2bfloat162_rn(v1.x, v1.y);
                *reinterpret_cast<__nv_bfloat162*>(Cb + (size_t)r * N + c) = p0;
                *reinterpret_cast<__nv_bfloat162*>(Cb + (size_t)(r + 8) * N + c) = p1;
            } else {  // OM == 3: transposed bf16 (vT[col][row])
                Cb[(size_t)c * M + r]           = __float2bfloat16(v0.x);
                Cb[(size_t)(c + 1) * M + r]     = __float2bfloat16(v0.y);
                Cb[(size_t)c * M + r + 8]       = __float2bfloat16(v1.x);
                Cb[(size_t)(c + 1) * M + r + 8] = __float2bfloat16(v1.y);
            }
        }
    }
}

// ---------------- BF16 flash attention (m16n8k16) ------------------------------
// Q/K smem [row][d] bf16 (36-word rows); V smem [d][key] bf16 (from global vT).
// P packed bf16x2 into Ps (aliases Qs). Softmax fp32 (unchanged).
#define QST 36
#define ATT_SMEM ((128*QST + 2*64*QST + 2*64*QST) * 4)

__global__ void __launch_bounds__(256, 2) attn_tc(
    const __nv_bfloat16* __restrict__ qb, const __nv_bfloat16* __restrict__ kb,
    const __nv_bfloat16* __restrict__ vT, float* __restrict__ og)
{
    extern __shared__ unsigned sma[];
    unsigned* Qs = sma;
    unsigned* Ps = Qs;                      // alias (Q frags preloaded to regs)

    const int tid  = threadIdx.x;
    const int warp = tid >> 5, lane = tid & 31;
    const int g    = lane >> 2, q4 = lane & 3;
    const int bh   = blockIdx.y;
    const int b    = bh >> 4, h = bh & 15;
    const int q0   = blockIdx.x * 128;
    const size_t rbase = (size_t)b * SSQ;
    const int r0 = warp << 4;
    const unsigned sbase = (unsigned)__cvta_generic_to_shared(sma);
    const unsigned ksb = sbase + 128 * QST * 4;
    const unsigned vsb = ksb + 2 * 64 * QST * 4;

    // Q tile: 128 rows x 64 bf16 = 1024 cp16
    #pragma unroll
    for (int i = 0; i < 4; i++) {
        int f = tid + (i << 8);
        int row = f >> 3, seg = f & 7;
        cp16(sbase + (row * QST + seg * 4) * 4,
             qb + ((rbase + q0 + row) << 10) + (h << 6) + (seg << 3));
    }
    CP_COMMIT();

    #define A_ISSUE(buf, kt) do { \
        _Pragma("unroll") \
        for (int i_ = 0; i_ < 2; i_++) { \
            int f_ = tid + (i_ << 8); \
            int rr_ = f_ >> 3, sg_ = f_ & 7; \
            cp16(ksb + ((buf) * 64 * QST + rr_ * QST + sg_ * 4) * 4, \
                 kb + ((rbase + (kt) + rr_) << 10) + (h << 6) + (sg_ << 3)); \
            cp16(vsb + ((buf) * 64 * QST + rr_ * QST + sg_ * 4) * 4, \
                 vT + (size_t)((h << 6) + rr_) * MTOT + rbase + (kt) + (sg_ << 3)); \
        } \
    } while (0)

    CP_WAIT(0);
    __syncthreads();
    // preload Q fragments: 4 k16 steps
    unsigned aq[4][4];
    #pragma unroll
    for (int ks = 0; ks < 4; ks++) {
        aq[ks][0] = Qs[(r0 + g) * QST + (ks << 3) + q4];
        aq[ks][1] = Qs[(r0 + 8 + g) * QST + (ks << 3) + q4];
        aq[ks][2] = Qs[(r0 + g) * QST + (ks << 3) + q4 + 4];
        aq[ks][3] = Qs[(r0 + 8 + g) * QST + (ks << 3) + q4 + 4];
    }

    A_ISSUE(0, 0);
    CP_COMMIT();

    float m0 = -1e30f, m1 = -1e30f, l0 = 0.f, l1 = 0.f;
    float oacc[8][4];
    #pragma unroll
    for (int j = 0; j < 8; j++)
        #pragma unroll
        for (int e = 0; e < 4; e++) oacc[j][e] = 0.f;

    const int NKT = SSQ / 64;
    for (int t = 0; t < NKT; t++) {
        __syncthreads();
        if (t + 1 < NKT) A_ISSUE((t + 1) & 1, (t + 1) * 64);
        CP_COMMIT();
        CP_WAIT(1);
        __syncthreads();

        const unsigned* Kb = reinterpret_cast<unsigned*>(sma) + 128 * QST + (t & 1) * 64 * QST;
        const unsigned* Vb = Kb + (2 - (t & 1)) * 64 * QST + (t & 1) * 2 * 64 * QST;
        // simpler: Vb = sma + 128*QST + 2*64*QST + (t&1)*64*QST
        Vb = sma + 128 * QST + 2 * 64 * QST + (t & 1) * 64 * QST;

        // S = Q K^T  (bf16 m16n8k16): 4 k16-steps x 8 key-groups
        float s[8][4];
        #pragma unroll
        for (int j = 0; j < 8; j++)
            #pragma unroll
            for (int e = 0; e < 4; e++) s[j][e] = 0.f;
        #pragma unroll
        for (int ks = 0; ks < 4; ks++) {
            #pragma unroll
            for (int j = 0; j < 8; j++) {
                unsigned b0 = Kb[((j << 3) + g) * QST + (ks << 3) + q4];
                unsigned b1 = Kb[((j << 3) + g) * QST + (ks << 3) + q4 + 4];
                MMA_BF16(s[j], aq[ks][0], aq[ks][1], aq[ks][2], aq[ks][3], b0, b1);
            }
        }

        // online softmax (fp32, unchanged)
        float mt0 = -1e30f, mt1 = -1e30f;
        #pragma unroll
        for (int j = 0; j < 8; j++) {
            s[j][0] *= 0.125f; s[j][1] *= 0.125f; s[j][2] *= 0.125f; s[j][3] *= 0.125f;
            mt0 = fmaxf(mt0, fmaxf(s[j][0], s[j][1]));
            mt1 = fmaxf(mt1, fmaxf(s[j][2], s[j][3]));
        }
        mt0 = fmaxf(mt0, __shfl_xor_sync(0xffffffffu, mt0, 1));
        mt0 = fmaxf(mt0, __shfl_xor_sync(0xffffffffu, mt0, 2));
        mt1 = fmaxf(mt1, __shfl_xor_sync(0xffffffffu, mt1, 1));
        mt1 = fmaxf(mt1, __shfl_xor_sync(0xffffffffu, mt1, 2));
        float mn0 = fmaxf(m0, mt0), mn1 = fmaxf(m1, mt1);
        float corr0 = __expf(m0 - mn0), corr1 = __expf(m1 - mn1);
        m0 = mn0; m1 = mn1;
        float ls0 = 0.f, ls1 = 0.f;
        #pragma unroll
        for (int j = 0; j < 8; j++) {
            float p0 = __expf(s[j][0] - mn0);
            float p1 = __expf(s[j][1] - mn0);
            float p2 = __expf(s[j][2] - mn1);
            float p3 = __expf(s[j][3] - mn1);
            ls0 += p0 + p1; ls1 += p2 + p3;
            __nv_bfloat162 pk0 = __floats2bfloat162_rn(p0, p1);
            __nv_bfloat162 pk1 = __floats2bfloat162_rn(p2, p3);
            // keys j*8 + 2q, 2q+1  -> word j*4 + q
            *reinterpret_cast<__nv_bfloat162*>(Ps + (r0 + g) * QST + (j << 2) + q4) = pk0;
            *reinterpret_cast<__nv_bfloat162*>(Ps + (r0 + 8 + g) * QST + (j << 2) + q4) = pk1;
        }
        ls0 += __shfl_xor_sync(0xffffffffu, ls0, 1);
        ls0 += __shfl_xor_sync(0xffffffffu, ls0, 2);
        ls1 += __shfl_xor_sync(0xffffffffu, ls1, 1);
        ls1 += __shfl_xor_sync(0xffffffffu, ls1, 2);
        l0 = l0 * corr0 + ls0;
        l1 = l1 * corr1 + ls1;
        #pragma unroll
        for (int j = 0; j < 8; j++) {
            oacc[j][0] *= corr0; oacc[j][1] *= corr0;
            oacc[j][2] *= corr1; oacc[j][3] *= corr1;
        }
        __syncwarp();

        // O += P @ V   (A = P from Ps, B = V^T from Vs[d][key])
        #pragma unroll
        for (int ks = 0; ks < 4; ks++) {
            unsigned ap0 = Ps[(r0 + g) * QST + (ks << 3) + q4];
            unsigned ap1 = Ps[(r0 + 8 + g) * QST + (ks << 3) + q4];
            unsigned ap2 = Ps[(r0 + g) * QST + (ks << 3) + q4 + 4];
            unsigned ap3 = Ps[(r0 + 8 + g) * QST + (ks << 3) + q4 + 4];
            #pragma unroll
            for (int j = 0; j < 8; j++) {
                unsigned b0 = Vb[((j << 3) + g) * QST + (ks << 3) + q4];
                unsigned b1 = Vb[((j << 3) + g) * QST + (ks << 3) + q4 + 4];
                MMA_BF16(oacc[j], ap0, ap1, ap2, ap3, b0, b1);
            }
        }
    }

    // epilogue (tf32-rounded fp32: feeds Wo GEMM)
    const size_t obase = rbase * DIMX + (size_t)h * HD;
    float il0 = 1.0f / l0, il1 = 1.0f / l1;
    #pragma unroll
    for (int j = 0; j < 8; j++) {
        uint2 v0, v1;
        v0.x = f2tf(oacc[j][0] * il0); v0.y = f2tf(oacc[j][1] * il0);
        v1.x = f2tf(oacc[j][2] * il1); v1.y = f2tf(oacc[j][3] * il1);
        size_t o0 = obase + (size_t)(q0 + r0 + g) * DIMX + (j << 3) + (q4 << 1);
        size_t o1 = obase + (size_t)(q0 + r0 + 8 + g) * DIMX + (j << 3) + (q4 << 1);
        *reinterpret_cast<uint2*>(og + o0) = v0;
        *reinterpret_cast<uint2*>(og + o1) = v1;
    }
}

// ---------------- launch ------------------------------------------------------
extern "C" void kernel_launch(void* const* d_in, const int* in_sizes, int n_in,
                              void* d_out, int out_size)
{
    const float* x    = (const float*)d_in[0];
    const float* wq   = (const float*)d_in[2];
    const float* wk   = (const float*)d_in[3];
    const float* wv   = (const float*)d_in[4];
    const float* wo   = (const float*)d_in[5];
    const float* w_up = (const float*)d_in[6];
    const float* b_up = (const float*)d_in[7];
    const float* w_dn = (const float*)d_in[8];
    const float* b_dn = (const float*)d_in[9];
    const float* l1a  = (const float*)d_in[10];
    const float* l1b  = (const float*)d_in[11];
    const float* l2a  = (const float*)d_in[12];
    const float* l2b  = (const float*)d_in[13];
    float* out = (float*)d_out;

    float *h, *attn, *x2, *ffh, *wc;
    __nv_bfloat16 *qb16, *kb16, *vT16;
    {
        void* p;
        cudaGetSymbolAddress(&p, g_h);    h    = (float*)p;
        cudaGetSymbolAddress(&p, g_q);    qb16 = (__nv_bfloat16*)p;
        cudaGetSymbolAddress(&p, g_k);    kb16 = (__nv_bfloat16*)p;
        cudaGetSymbolAddress(&p, g_v);    vT16 = (__nv_bfloat16*)p;
        cudaGetSymbolAddress(&p, g_attn); attn = (float*)p;
        cudaGetSymbolAddress(&p, g_x2);   x2   = (float*)p;
        cudaGetSymbolAddress(&p, g_ffh);  ffh  = (float*)p;
        cudaGetSymbolAddress(&p, g_wc);   wc   = (float*)p;
    }

    float* wq_c = wc;
    float* wk_c = wc + 1 * DIMX * DIMX;
    float* wv_c = wc + 2 * DIMX * DIMX;
    float* wo_c = wc + 3 * DIMX * DIMX;
    float* wu_c = wc + 4 * DIMX * DIMX;
    float* wd_c = wu_c + DIMX * DFF;

    cudaFuncSetAttribute(gemm_tc<2,false,false,false>, cudaFuncAttributeMaxDynamicSharedMemorySize, GEMM_SMEM);
    cudaFuncSetAttribute(gemm_tc<3,false,false,false>, cudaFuncAttributeMaxDynamicSharedMemorySize, GEMM_SMEM);
    cudaFuncSetAttribute(gemm_tc<0,false,false,true >, cudaFuncAttributeMaxDynamicSharedMemorySize, GEMM_SMEM);
    cudaFuncSetAttribute(gemm_tc<1,true ,true ,false>, cudaFuncAttributeMaxDynamicSharedMemorySize, GEMM_SMEM);
    cudaFuncSetAttribute(gemm_tc<0,true ,false,true >, cudaFuncAttributeMaxDynamicSharedMemorySize, GEMM_SMEM);
    cudaFuncSetAttribute(attn_tc, cudaFuncAttributeMaxDynamicSharedMemorySize, ATT_SMEM);

    dim3 thr(256);

    // 0: weight convert
    prep_all<<<(WTOT + 255) / 256, thr>>>(wq, wk, wv, wo, w_up, w_dn, wc);

    // 1: h = LN1(x)  (tf32)
    ln_kernel<<<MTOT, thr>>>(x, l1a, l1b, h);

    // 2,3: Q,K projections -> bf16 rows
    gemm_tc<2,false,false,false><<<dim3(DIMX/128, MTOT/128), thr, GEMM_SMEM>>>(h, wq_c, nullptr, nullptr, nullptr, qb16, MTOT, DIMX, DIMX);
    gemm_tc<2,false,false,false><<<dim3(DIMX/128, MTOT/128), thr, GEMM_SMEM>>>(h, wk_c, nullptr, nullptr, nullptr, kb16, MTOT, DIMX, DIMX);

    // 4: V projection -> bf16 transposed (vT[d_global][token])
    gemm_tc<3,false,false,false><<<dim3(DIMX/128, MTOT/128), thr, GEMM_SMEM>>>(h, wv_c, nullptr, nullptr, nullptr, vT16, MTOT, DIMX, DIMX);

    // 5: attention (bf16 mma) -> attn (tf32 fp32)
    attn_tc<<<dim3(SSQ/128, BB*NH), thr, ATT_SMEM>>>(qb16, kb16, vT16, attn);

    // 6: x2 = x + attn @ wo
    gemm_tc<0,false,false,true><<<dim3(DIMX/128, MTOT/128), thr, GEMM_SMEM>>>(attn, wo_c, nullptr, x, x2, nullptr, MTOT, DIMX, DIMX);

    // 7: h = LN2(x2)
    ln_kernel<<<MTOT, thr>>>(x2, l2a, l2b, h);

    // 8: ffh = relu(h @ w_up + b_up)  (tf32 out)
    gemm_tc<1,true,true,false><<<dim3(DFF/128, MTOT/128), thr, GEMM_SMEM>>>(h, wu_c, b_up, nullptr, ffh, nullptr, MTOT, DFF, DIMX);

    // 9: out = x2 + ffh @ w_down + b_down
    gemm_tc<0,true,false,true><<<dim3(DIMX/128, MTOT/128), thr, GEMM_SMEM>>>(ffh, wd_c, b_dn, x2, out, nullptr, MTOT, DIMX, DFF);
}

// round 12
// speedup vs baseline: 1.7163x; 1.3871x over previous
#include <cuda_runtime.h>
#include <cuda_fp16.h>
#include <math.h>

#define DIMX 1024
#define NH   16
#define HD   64
#define DFF  4096
#define BB   2
#define SSQ  2048
#define MTOT (BB*SSQ)
#define EPSV 1e-6f

// ---------------- scratch (device globals) ----------------------------------
__device__ __align__(256) __half g_h   [MTOT*DIMX];
__device__ __align__(256) __half g_q   [MTOT*DIMX];
__device__ __align__(256) __half g_k   [MTOT*DIMX];
__device__ __align__(256) __half g_v   [MTOT*DIMX];   // vT [1024][MTOT]
__device__ __align__(256) __half g_attn[MTOT*DIMX];
__device__ __align__(256) float  g_x2  [MTOT*DIMX];
__device__ __align__(256) __half g_ffh [MTOT*DFF];
__device__ __align__(256) __half g_wt  [12*1024*1024];  // transposed fp16 weights

// ---------------- helpers ----------------------------------------------------
__device__ __forceinline__ void cp16(unsigned s, const void* g) {
    asm volatile("cp.async.cg.shared.global [%0], [%1], 16;" :: "r"(s), "l"(g));
}
#define CP_COMMIT() asm volatile("cp.async.commit_group;")
#define CP_WAIT(n)  asm volatile("cp.async.wait_group %0;" :: "n"(n))

#define MMA_F16(c, a0, a1, a2, a3, b0, b1) asm volatile( \
    "mma.sync.aligned.m16n8k16.row.col.f32.f16.f16.f32 " \
    "{%0,%1,%2,%3}, {%4,%5,%6,%7}, {%8,%9}, {%0,%1,%2,%3};" \
    : "+f"((c)[0]), "+f"((c)[1]), "+f"((c)[2]), "+f"((c)[3]) \
    : "r"(a0), "r"(a1), "r"(a2), "r"(a3), "r"(b0), "r"(b1))

// ---------------- weight prep: transpose [K,N]->[N,K] + fp16 ------------------
__global__ void __launch_bounds__(256) prep_wT(const float* __restrict__ w,
                                               __half* __restrict__ o, int K, int N)
{
    __shared__ float t[32][33];
    int kt = blockIdx.y << 5, nb = blockIdx.x << 5;
    int tid = threadIdx.x;
    #pragma unroll
    for (int i = 0; i < 4; i++) {
        int idx = tid + (i << 8);
        int r = idx >> 5, c = idx & 31;
        t[r][c] = w[(size_t)(kt + r) * N + nb + c];
    }
    __syncthreads();
    #pragma unroll
    for (int i = 0; i < 4; i++) {
        int idx = tid + (i << 8);
        int r = idx >> 5, c = idx & 31;   // r = n-local, c = k-local
        o[(size_t)(nb + r) * K + kt + c] = __float2half(t[c][r]);
    }
}

// ---------------- LayerNorm (emits fp16) --------------------------------------
__global__ void __launch_bounds__(256) ln_kernel(
    const float* __restrict__ x, const float* __restrict__ alpha,
    const float* __restrict__ beta, __half* __restrict__ y)
{
    int row = blockIdx.x;
    int t = threadIdx.x;
    const float4* xr = reinterpret_cast<const float4*>(x + (size_t)row * DIMX);
    float4 v = xr[t];
    float s  = v.x + v.y + v.z + v.w;
    float sq = v.x*v.x + v.y*v.y + v.z*v.z + v.w*v.w;
    #pragma unroll
    for (int o = 16; o; o >>= 1) {
        s  += __shfl_xor_sync(0xffffffffu, s,  o);
        sq += __shfl_xor_sync(0xffffffffu, sq, o);
    }
    __shared__ float ss[8], ssq[8];
    int w = t >> 5, l = t & 31;
    if (l == 0) { ss[w] = s; ssq[w] = sq; }
    __syncthreads();
    if (w == 0) {
        s  = (l < 8) ? ss[l]  : 0.f;
        sq = (l < 8) ? ssq[l] : 0.f;
        #pragma unroll
        for (int o = 4; o; o >>= 1) {
            s  += __shfl_xor_sync(0xffffffffu, s,  o);
            sq += __shfl_xor_sync(0xffffffffu, sq, o);
        }
        if (l == 0) { ss[0] = s; ssq[0] = sq; }
    }
    __syncthreads();
    s = ss[0]; sq = ssq[0];
    float mu  = s * (1.0f / DIMX);
    float var = (sq - (float)DIMX * mu * mu) * (1.0f / (DIMX - 1));
    float sig = sqrtf(fmaxf(var, 0.f));
    float inv = 1.0f / (sig + EPSV);
    float4 a = reinterpret_cast<const float4*>(alpha)[t];
    float4 b = reinterpret_cast<const float4*>(beta)[t];
    __half2 h0 = __floats2half2_rn(a.x * (v.x - mu) * inv + b.x,
                                   a.y * (v.y - mu) * inv + b.y);
    __half2 h1 = __floats2half2_rn(a.z * (v.z - mu) * inv + b.z,
                                   a.w * (v.w - mu) * inv + b.w);
    size_t off = (size_t)row * DIMX + t * 4;
    reinterpret_cast<__half2*>(y + off)[0] = h0;
    reinterpret_cast<__half2*>(y + off)[1] = h1;
}

// ---------------- FP16 tensor GEMM (m16n8k16, round-8 pipeline) ---------------
// C[M,N] = A[M,K] @ Bt[N,K]^T, fp16 operands, fp32 accum. 128x128x32 tiles,
// 256 thr, warp tile 64x32, 3-stage cp.async, 2 CTA/SM.
// PW = 20 words (80 B) row pitch: 16B-aligned for cp.async, conflict-free LDS.
// OM: 0 = fp32 out (+res), 2 = fp16 rows, 3 = fp16 transposed (vT).
#define STAGES 3
#define PW 20
#define STAGE_U32 (256*PW)
#define GEMM_SMEM (STAGES * STAGE_U32 * 4)

template<int OM, bool BIAS, bool RELU, bool RES>
__global__ void __launch_bounds__(256, 2) gemm_fp16(
    const __half* __restrict__ A, const __half* __restrict__ Bt,
    const float* __restrict__ bias, const float* __restrict__ res,
    float* __restrict__ C, __half* __restrict__ Ch,
    int M, int N, int K)
{
    extern __shared__ unsigned smg[];
    const int tid  = threadIdx.x;
    const int bm   = blockIdx.y * 128, bn = blockIdx.x * 128;
    const int warp = tid >> 5, lane = tid & 31;
    const int wm   = (warp >> 2) << 6;
    const int wn   = (warp & 3) << 5;
    const int g    = lane >> 2, q = lane & 3;

    const unsigned sbase = (unsigned)__cvta_generic_to_shared(smg);

    float acc[4][4][4];
    #pragma unroll
    for (int mi = 0; mi < 4; mi++)
        #pragma unroll
        for (int nj = 0; nj < 4; nj++)
            #pragma unroll
            for (int e = 0; e < 4; e++) acc[mi][nj][e] = 0.f;

    const int nt = K >> 5;

    #define G_ISSUE(buf, kt) do { \
        unsigned ab_ = sbase + (buf) * (STAGE_U32 * 4); \
        unsigned bb_ = ab_ + 128 * PW * 4; \
        _Pragma("unroll") \
        for (int i_ = 0; i_ < 2; i_++) { \
            int idx_ = tid + (i_ << 8); \
            int row_ = idx_ >> 2, seg_ = idx_ & 3; \
            cp16(ab_ + (row_ * PW + seg_ * 4) * 4, \
                 A  + (size_t)(bm + row_) * K + (kt) * 32 + seg_ * 8); \
            cp16(bb_ + (row_ * PW + seg_ * 4) * 4, \
                 Bt + (size_t)(bn + row_) * K + (kt) * 32 + seg_ * 8); \
        } \
    } while (0)

    #pragma unroll
    for (int s = 0; s < STAGES - 1; s++) {
        if (s < nt) G_ISSUE(s, s);
        CP_COMMIT();
    }

    for (int kt = 0; kt < nt; kt++) {
        CP_WAIT(STAGES - 2);
        __syncthreads();
        int nl = kt + STAGES - 1;
        if (nl < nt) G_ISSUE(nl % STAGES, nl);
        CP_COMMIT();

        const unsigned* Ab = smg + (kt % STAGES) * STAGE_U32;
        const unsigned* Bb = Ab + 128 * PW;
        #pragma unroll
        for (int ks = 0; ks < 2; ks++) {
            const int kw = ks << 3;
            unsigned af[4][4], bf[4][2];
            #pragma unroll
            for (int mi = 0; mi < 4; mi++) {
                int r = wm + (mi << 4) + g;
                af[mi][0] = Ab[r * PW + kw + q];
                af[mi][1] = Ab[(r + 8) * PW + kw + q];
                af[mi][2] = Ab[r * PW + kw + q + 4];
                af[mi][3] = Ab[(r + 8) * PW + kw + q + 4];
            }
            #pragma unroll
            for (int nj = 0; nj < 4; nj++) {
                int c = wn + (nj << 3) + g;
                bf[nj][0] = Bb[c * PW + kw + q];
                bf[nj][1] = Bb[c * PW + kw + q + 4];
            }
            #pragma unroll
            for (int mi = 0; mi < 4; mi++)
                #pragma unroll
                for (int nj = 0; nj < 4; nj++)
                    MMA_F16(acc[mi][nj], af[mi][0], af[mi][1], af[mi][2], af[mi][3],
                            bf[nj][0], bf[nj][1]);
        }
    }

    // epilogue: thread owns rows g,g+8 / cols 2q,2q+1 of each 16x8 frag
    #pragma unroll
    for (int mi = 0; mi < 4; mi++) {
        int r = bm + wm + (mi << 4) + g;
        #pragma unroll
        for (int nj = 0; nj < 4; nj++) {
            int c = bn + wn + (nj << 3) + (q << 1);
            float2 v0, v1;
            v0.x = acc[mi][nj][0]; v0.y = acc[mi][nj][1];
            v1.x = acc[mi][nj][2]; v1.y = acc[mi][nj][3];
            if (BIAS) {
                float2 bv = *reinterpret_cast<const float2*>(bias + c);
                v0.x += bv.x; v0.y += bv.y; v1.x += bv.x; v1.y += bv.y;
            }
            if (RELU) {
                v0.x = fmaxf(v0.x, 0.f); v0.y = fmaxf(v0.y, 0.f);
                v1.x = fmaxf(v1.x, 0.f); v1.y = fmaxf(v1.y, 0.f);
            }
            if (RES) {
                float2 r0 = *reinterpret_cast<const float2*>(res + (size_t)r * N + c);
                float2 r1 = *reinterpret_cast<const float2*>(res + (size_t)(r + 8) * N + c);
                v0.x += r0.x; v0.y += r0.y; v1.x += r1.x; v1.y += r1.y;
            }
            if (OM == 0) {
                *reinterpret_cast<float2*>(C + (size_t)r * N + c) = v0;
                *reinterpret_cast<float2*>(C + (size_t)(r + 8) * N + c) = v1;
            } else if (OM == 2) {
                *reinterpret_cast<__half2*>(Ch + (size_t)r * N + c) = __floats2half2_rn(v0.x, v0.y);
                *reinterpret_cast<__half2*>(Ch + (size_t)(r + 8) * N + c) = __floats2half2_rn(v1.x, v1.y);
            } else {  // OM == 3: transposed fp16 (vT[col][row])
                Ch[(size_t)c * M + r]           = __float2half(v0.x);
                Ch[(size_t)(c + 1) * M + r]     = __float2half(v0.y);
                Ch[(size_t)c * M + r + 8]       = __float2half(v1.x);
                Ch[(size_t)(c + 1) * M + r + 8] = __float2half(v1.y);
            }
        }
    }
}

// ---------------- FP16 flash attention (m16n8k16, round-10 structure) ----------
#define QST 36
#define ATT_SMEM ((128*QST + 2*64*QST + 2*64*QST) * 4)

__global__ void __launch_bounds__(256, 2) attn_tc(
    const __half* __restrict__ qb, const __half* __restrict__ kb,
    const __half* __restrict__ vT, __half* __restrict__ og)
{
    extern __shared__ unsigned sma[];
    unsigned* Qs = sma;
    unsigned* Ps = Qs;                      // alias (Q frags preloaded to regs)

    const int tid  = threadIdx.x;
    const int warp = tid >> 5, lane = tid & 31;
    const int g    = lane >> 2, q4 = lane & 3;
    const int bh   = blockIdx.y;
    const int b    = bh >> 4, h = bh & 15;
    const int q0   = blockIdx.x * 128;
    const size_t rbase = (size_t)b * SSQ;
    const int r0 = warp << 4;
    const unsigned sbase = (unsigned)__cvta_generic_to_shared(sma);
    const unsigned ksb = sbase + 128 * QST * 4;
    const unsigned vsb = ksb + 2 * 64 * QST * 4;

    // Q tile: 128 rows x 64 fp16
    #pragma unroll
    for (int i = 0; i < 4; i++) {
        int f = tid + (i << 8);
        int row = f >> 3, seg = f & 7;
        cp16(sbase + (row * QST + seg * 4) * 4,
             qb + ((rbase + q0 + row) << 10) + (h << 6) + (seg << 3));
    }
    CP_COMMIT();

    #define A_ISSUE(buf, kt) do { \
        _Pragma("unroll") \
        for (int i_ = 0; i_ < 2; i_++) { \
            int f_ = tid + (i_ << 8); \
            int rr_ = f_ >> 3, sg_ = f_ & 7; \
            cp16(ksb + ((buf) * 64 * QST + rr_ * QST + sg_ * 4) * 4, \
                 kb + ((rbase + (kt) + rr_) << 10) + (h << 6) + (sg_ << 3)); \
            cp16(vsb + ((buf) * 64 * QST + rr_ * QST + sg_ * 4) * 4, \
                 vT + (size_t)((h << 6) + rr_) * MTOT + rbase + (kt) + (sg_ << 3)); \
        } \
    } while (0)

    CP_WAIT(0);
    __syncthreads();
    unsigned aq[4][4];
    #pragma unroll
    for (int ks = 0; ks < 4; ks++) {
        aq[ks][0] = Qs[(r0 + g) * QST + (ks << 3) + q4];
        aq[ks][1] = Qs[(r0 + 8 + g) * QST + (ks << 3) + q4];
        aq[ks][2] = Qs[(r0 + g) * QST + (ks << 3) + q4 + 4];
        aq[ks][3] = Qs[(r0 + 8 + g) * QST + (ks << 3) + q4 + 4];
    }

    A_ISSUE(0, 0);
    CP_COMMIT();

    float m0 = -1e30f, m1 = -1e30f, l0 = 0.f, l1 = 0.f;
    float oacc[8][4];
    #pragma unroll
    for (int j = 0; j < 8; j++)
        #pragma unroll
        for (int e = 0; e < 4; e++) oacc[j][e] = 0.f;

    const int NKT = SSQ / 64;
    for (int t = 0; t < NKT; t++) {
        __syncthreads();
        if (t + 1 < NKT) A_ISSUE((t + 1) & 1, (t + 1) * 64);
        CP_COMMIT();
        CP_WAIT(1);
        __syncthreads();

        const unsigned* Kb = sma + 128 * QST + (t & 1) * 64 * QST;
        const unsigned* Vb = sma + 128 * QST + 2 * 64 * QST + (t & 1) * 64 * QST;

        // S = Q K^T
        float s[8][4];
        #pragma unroll
        for (int j = 0; j < 8; j++)
            #pragma unroll
            for (int e = 0; e < 4; e++) s[j][e] = 0.f;
        #pragma unroll
        for (int ks = 0; ks < 4; ks++) {
            #pragma unroll
            for (int j = 0; j < 8; j++) {
                unsigned b0 = Kb[((j << 3) + g) * QST + (ks << 3) + q4];
                unsigned b1 = Kb[((j << 3) + g) * QST + (ks << 3) + q4 + 4];
                MMA_F16(s[j], aq[ks][0], aq[ks][1], aq[ks][2], aq[ks][3], b0, b1);
            }
        }

        // online softmax (fp32)
        float mt0 = -1e30f, mt1 = -1e30f;
        #pragma unroll
        for (int j = 0; j < 8; j++) {
            s[j][0] *= 0.125f; s[j][1] *= 0.125f; s[j][2] *= 0.125f; s[j][3] *= 0.125f;
            mt0 = fmaxf(mt0, fmaxf(s[j][0], s[j][1]));
            mt1 = fmaxf(mt1, fmaxf(s[j][2], s[j][3]));
        }
        mt0 = fmaxf(mt0, __shfl_xor_sync(0xffffffffu, mt0, 1));
        mt0 = fmaxf(mt0, __shfl_xor_sync(0xffffffffu, mt0, 2));
        mt1 = fmaxf(mt1, __shfl_xor_sync(0xffffffffu, mt1, 1));
        mt1 = fmaxf(mt1, __shfl_xor_sync(0xffffffffu, mt1, 2));
        float mn0 = fmaxf(m0, mt0), mn1 = fmaxf(m1, mt1);
        float corr0 = __expf(m0 - mn0), corr1 = __expf(m1 - mn1);
        m0 = mn0; m1 = mn1;
        float ls0 = 0.f, ls1 = 0.f;
        #pragma unroll
        for (int j = 0; j < 8; j++) {
            float p0 = __expf(s[j][0] - mn0);
            float p1 = __expf(s[j][1] - mn0);
            float p2 = __expf(s[j][2] - mn1);
            float p3 = __expf(s[j][3] - mn1);
            ls0 += p0 + p1; ls1 += p2 + p3;
            *reinterpret_cast<__half2*>(Ps + (r0 + g) * QST + (j << 2) + q4) =
                __floats2half2_rn(p0, p1);
            *reinterpret_cast<__half2*>(Ps + (r0 + 8 + g) * QST + (j << 2) + q4) =
                __floats2half2_rn(p2, p3);
        }
        ls0 += __shfl_xor_sync(0xffffffffu, ls0, 1);
        ls0 += __shfl_xor_sync(0xffffffffu, ls0, 2);
        ls1 += __shfl_xor_sync(0xffffffffu, ls1, 1);
        ls1 += __shfl_xor_sync(0xffffffffu, ls1, 2);
        l0 = l0 * corr0 + ls0;
        l1 = l1 * corr1 + ls1;
        #pragma unroll
        for (int j = 0; j < 8; j++) {
            oacc[j][0] *= corr0; oacc[j][1] *= corr0;
            oacc[j][2] *= corr1; oacc[j][3] *= corr1;
        }
        __syncwarp();

        // O += P @ V  (B = V^T[d][key] from Vs)
        #pragma unroll
        for (int ks = 0; ks < 4; ks++) {
            unsigned ap0 = Ps[(r0 + g) * QST + (ks << 3) + q4];
            unsigned ap1 = Ps[(r0 + 8 + g) * QST + (ks << 3) + q4];
            unsigned ap2 = Ps[(r0 + g) * QST + (ks << 3) + q4 + 4];
            unsigned ap3 = Ps[(r0 + 8 + g) * QST + (ks << 3) + q4 + 4];
            #pragma unroll
            for (int j = 0; j < 8; j++) {
                unsigned b0 = Vb[((j << 3) + g) * QST + (ks << 3) + q4];
                unsigned b1 = Vb[((j << 3) + g) * QST + (ks << 3) + q4 + 4];
                MMA_F16(oacc[j], ap0, ap1, ap2, ap3, b0, b1);
            }
        }
    }

    // epilogue: fp16 rows (feeds Wo GEMM)
    const size_t obase = rbase * DIMX + (size_t)h * HD;
    float il0 = 1.0f / l0, il1 = 1.0f / l1;
    #pragma unroll
    for (int j = 0; j < 8; j++) {
        size_t o0 = obase + (size_t)(q0 + r0 + g) * DIMX + (j << 3) + (q4 << 1);
        size_t o1 = obase + (size_t)(q0 + r0 + 8 + g) * DIMX + (j << 3) + (q4 << 1);
        *reinterpret_cast<__half2*>(og + o0) =
            __floats2half2_rn(oacc[j][0] * il0, oacc[j][1] * il0);
        *reinterpret_cast<__half2*>(og + o1) =
            __floats2half2_rn(oacc[j][2] * il1, oacc[j][3] * il1);
    }
}

// ---------------- launch ------------------------------------------------------
extern "C" void kernel_launch(void* const* d_in, const int* in_sizes, int n_in,
                              void* d_out, int out_size)
{
    const float* x    = (const float*)d_in[0];
    const float* wq   = (const float*)d_in[2];
    const float* wk   = (const float*)d_in[3];
    const float* wv   = (const float*)d_in[4];
    const float* wo   = (const float*)d_in[5];
    const float* w_up = (const float*)d_in[6];
    const float* b_up = (const float*)d_in[7];
    const float* w_dn = (const float*)d_in[8];
    const float* b_dn = (const float*)d_in[9];
    const float* l1a  = (const float*)d_in[10];
    const float* l1b  = (const float*)d_in[11];
    const float* l2a  = (const float*)d_in[12];
    const float* l2b  = (const float*)d_in[13];
    float* out = (float*)d_out;

    __half *h, *qb, *kb, *vT, *attn, *ffh, *wt;
    float *x2;
    {
        void* p;
        cudaGetSymbolAddress(&p, g_h);    h    = (__half*)p;
        cudaGetSymbolAddress(&p, g_q);    qb   = (__half*)p;
        cudaGetSymbolAddress(&p, g_k);    kb   = (__half*)p;
        cudaGetSymbolAddress(&p, g_v);    vT   = (__half*)p;
        cudaGetSymbolAddress(&p, g_attn); attn = (__half*)p;
        cudaGetSymbolAddress(&p, g_x2);   x2   = (float*)p;
        cudaGetSymbolAddress(&p, g_ffh);  ffh  = (__half*)p;
        cudaGetSymbolAddress(&p, g_wt);   wt   = (__half*)p;
    }

    __half* wq_t = wt;                         // [1024,1024]
    __half* wk_t = wt + 1 * 1024 * 1024;
    __half* wv_t = wt + 2 * 1024 * 1024;
    __half* wo_t = wt + 3 * 1024 * 1024;
    __half* wu_t = wt + 4 * 1024 * 1024;       // [4096,1024]
    __half* wd_t = wt + 8 * 1024 * 1024;       // [1024,4096]

    cudaFuncSetAttribute(gemm_fp16<2,false,false,false>, cudaFuncAttributeMaxDynamicSharedMemorySize, GEMM_SMEM);
    cudaFuncSetAttribute(gemm_fp16<3,false,false,false>, cudaFuncAttributeMaxDynamicSharedMemorySize, GEMM_SMEM);
    cudaFuncSetAttribute(gemm_fp16<0,false,false,true >, cudaFuncAttributeMaxDynamicSharedMemorySize, GEMM_SMEM);
    cudaFuncSetAttribute(gemm_fp16<2,true ,true ,false>, cudaFuncAttributeMaxDynamicSharedMemorySize, GEMM_SMEM);
    cudaFuncSetAttribute(gemm_fp16<0,true ,false,true >, cudaFuncAttributeMaxDynamicSharedMemorySize, GEMM_SMEM);
    cudaFuncSetAttribute(attn_tc, cudaFuncAttributeMaxDynamicSharedMemorySize, ATT_SMEM);

    dim3 thr(256);

    // weight prep: transpose + fp16
    prep_wT<<<dim3(DIMX/32, DIMX/32), thr>>>(wq,   wq_t, DIMX, DIMX);
    prep_wT<<<dim3(DIMX/32, DIMX/32), thr>>>(wk,   wk_t, DIMX, DIMX);
    prep_wT<<<dim3(DIMX/32, DIMX/32), thr>>>(wv,   wv_t, DIMX, DIMX);
    prep_wT<<<dim3(DIMX/32, DIMX/32), thr>>>(wo,   wo_t, DIMX, DIMX);
    prep_wT<<<dim3(DFF/32,  DIMX/32), thr>>>(w_up, wu_t, DIMX, DFF);
    prep_wT<<<dim3(DIMX/32, DFF/32),  thr>>>(w_dn, wd_t, DFF,  DIMX);

    // h = LN1(x)  (fp16)
    ln_kernel<<<MTOT, thr>>>(x, l1a, l1b, h);

    // Q,K projections -> fp16 rows
    gemm_fp16<2,false,false,false><<<dim3(DIMX/128, MTOT/128), thr, GEMM_SMEM>>>(h, wq_t, nullptr, nullptr, nullptr, qb, MTOT, DIMX, DIMX);
    gemm_fp16<2,false,false,false><<<dim3(DIMX/128, MTOT/128), thr, GEMM_SMEM>>>(h, wk_t, nullptr, nullptr, nullptr, kb, MTOT, DIMX, DIMX);

    // V projection -> fp16 transposed
    gemm_fp16<3,false,false,false><<<dim3(DIMX/128, MTOT/128), thr, GEMM_SMEM>>>(h, wv_t, nullptr, nullptr, nullptr, vT, MTOT, DIMX, DIMX);

    // attention -> attn (fp16 rows)
    attn_tc<<<dim3(SSQ/128, BB*NH), thr, ATT_SMEM>>>(qb, kb, vT, attn);

    // x2 = x + attn @ wo  (fp32)
    gemm_fp16<0,false,false,true><<<dim3(DIMX/128, MTOT/128), thr, GEMM_SMEM>>>(attn, wo_t, nullptr, x, x2, nullptr, MTOT, DIMX, DIMX);

    // h = LN2(x2)  (fp16)
    ln_kernel<<<MTOT, thr>>>(x2, l2a, l2b, h);

    // ffh = relu(h @ w_up + b_up)  (fp16)
    gemm_fp16<2,true,true,false><<<dim3(DFF/128, MTOT/128), thr, GEMM_SMEM>>>(h, wu_t, b_up, nullptr, nullptr, ffh, MTOT, DFF, DIMX);

    // out = x2 + ffh @ w_down + b_down  (fp32)
    gemm_fp16<0,true,false,true><<<dim3(DIMX/128, MTOT/128), thr, GEMM_SMEM>>>(ffh, wd_t, b_dn, x2, out, nullptr, MTOT, DIMX, DFF);
}

// round 13
// speedup vs baseline: 1.7285x; 1.0071x over previous
#include <cuda_runtime.h>
#include <cuda_fp16.h>
#include <math.h>

#define DIMX 1024
#define NH   16
#define HD   64
#define DFF  4096
#define BB   2
#define SSQ  2048
#define MTOT (BB*SSQ)
#define EPSV 1e-6f

// ---------------- scratch (device globals) ----------------------------------
__device__ __align__(256) __half g_h   [MTOT*DIMX];
__device__ __align__(256) __half g_q   [MTOT*DIMX];
__device__ __align__(256) __half g_k   [MTOT*DIMX];
__device__ __align__(256) __half g_v   [MTOT*DIMX];   // vT [1024][MTOT]
__device__ __align__(256) __half g_attn[MTOT*DIMX];
__device__ __align__(256) float  g_x2  [MTOT*DIMX];
__device__ __align__(256) __half g_ffh [MTOT*DFF];
__device__ __align__(256) __half g_wt  [12*1024*1024];  // transposed fp16 weights

// ---------------- helpers ----------------------------------------------------
__device__ __forceinline__ void cp16(unsigned s, const void* g) {
    asm volatile("cp.async.cg.shared.global [%0], [%1], 16;" :: "r"(s), "l"(g));
}
#define CP_COMMIT() asm volatile("cp.async.commit_group;")
#define CP_WAIT(n)  asm volatile("cp.async.wait_group %0;" :: "n"(n))

#define MMA_F16(c, a0, a1, a2, a3, b0, b1) asm volatile( \
    "mma.sync.aligned.m16n8k16.row.col.f32.f16.f16.f32 " \
    "{%0,%1,%2,%3}, {%4,%5,%6,%7}, {%8,%9}, {%0,%1,%2,%3};" \
    : "+f"((c)[0]), "+f"((c)[1]), "+f"((c)[2]), "+f"((c)[3]) \
    : "r"(a0), "r"(a1), "r"(a2), "r"(a3), "r"(b0), "r"(b1))

// ---------------- merged weight prep: all 6 transposes in ONE launch ----------
// tile map: wq 0-1023, wk 1024-2047, wv 2048-3071, wo 3072-4095,
//           wu 4096-8191 (N=4096), wd 8192-12287 (K=4096)
__global__ void __launch_bounds__(256) prep_all_T(
    const float* __restrict__ wq, const float* __restrict__ wk,
    const float* __restrict__ wv, const float* __restrict__ wo,
    const float* __restrict__ wu, const float* __restrict__ wd,
    __half* __restrict__ wt)
{
    __shared__ float t[32][33];
    int bid = blockIdx.x;
    const float* w; __half* o; int K, N, tile;
    if      (bid < 1024) { w = wq; o = wt;                 K = 1024; N = 1024; tile = bid; }
    else if (bid < 2048) { w = wk; o = wt + 1*1024*1024;   K = 1024; N = 1024; tile = bid - 1024; }
    else if (bid < 3072) { w = wv; o = wt + 2*1024*1024;   K = 1024; N = 1024; tile = bid - 2048; }
    else if (bid < 4096) { w = wo; o = wt + 3*1024*1024;   K = 1024; N = 1024; tile = bid - 3072; }
    else if (bid < 8192) { w = wu; o = wt + 4*1024*1024;   K = 1024; N = 4096; tile = bid - 4096; }
    else                 { w = wd; o = wt + 8*1024*1024;   K = 4096; N = 1024; tile = bid - 8192; }
    int ntN = N >> 5;
    int nb = (tile % ntN) << 5;
    int kt = (tile / ntN) << 5;
    int tid = threadIdx.x;
    #pragma unroll
    for (int i = 0; i < 4; i++) {
        int idx = tid + (i << 8);
        int r = idx >> 5, c = idx & 31;
        t[r][c] = w[(size_t)(kt + r) * N + nb + c];
    }
    __syncthreads();
    #pragma unroll
    for (int i = 0; i < 4; i++) {
        int idx = tid + (i << 8);
        int r = idx >> 5, c = idx & 31;   // r = n-local, c = k-local
        o[(size_t)(nb + r) * K + kt + c] = __float2half(t[c][r]);
    }
}

// ---------------- LayerNorm (emits fp16) --------------------------------------
__global__ void __launch_bounds__(256) ln_kernel(
    const float* __restrict__ x, const float* __restrict__ alpha,
    const float* __restrict__ beta, __half* __restrict__ y)
{
    int row = blockIdx.x;
    int t = threadIdx.x;
    const float4* xr = reinterpret_cast<const float4*>(x + (size_t)row * DIMX);
    float4 v = xr[t];
    float s  = v.x + v.y + v.z + v.w;
    float sq = v.x*v.x + v.y*v.y + v.z*v.z + v.w*v.w;
    #pragma unroll
    for (int o = 16; o; o >>= 1) {
        s  += __shfl_xor_sync(0xffffffffu, s,  o);
        sq += __shfl_xor_sync(0xffffffffu, sq, o);
    }
    __shared__ float ss[8], ssq[8];
    int w = t >> 5, l = t & 31;
    if (l == 0) { ss[w] = s; ssq[w] = sq; }
    __syncthreads();
    if (w == 0) {
        s  = (l < 8) ? ss[l]  : 0.f;
        sq = (l < 8) ? ssq[l] : 0.f;
        #pragma unroll
        for (int o = 4; o; o >>= 1) {
            s  += __shfl_xor_sync(0xffffffffu, s,  o);
            sq += __shfl_xor_sync(0xffffffffu, sq, o);
        }
        if (l == 0) { ss[0] = s; ssq[0] = sq; }
    }
    __syncthreads();
    s = ss[0]; sq = ssq[0];
    float mu  = s * (1.0f / DIMX);
    float var = (sq - (float)DIMX * mu * mu) * (1.0f / (DIMX - 1));
    float sig = sqrtf(fmaxf(var, 0.f));
    float inv = 1.0f / (sig + EPSV);
    float4 a = reinterpret_cast<const float4*>(alpha)[t];
    float4 b = reinterpret_cast<const float4*>(beta)[t];
    __half2 h0 = __floats2half2_rn(a.x * (v.x - mu) * inv + b.x,
                                   a.y * (v.y - mu) * inv + b.y);
    __half2 h1 = __floats2half2_rn(a.z * (v.z - mu) * inv + b.z,
                                   a.w * (v.w - mu) * inv + b.w);
    size_t off = (size_t)row * DIMX + t * 4;
    reinterpret_cast<__half2*>(y + off)[0] = h0;
    reinterpret_cast<__half2*>(y + off)[1] = h1;
}

// ---------------- FP16 tensor GEMM (m16n8k16, 4-stage cp.async) ---------------
// C[M,N] = A[M,K] @ Bt[N,K]^T. 128x128x32 tiles, 256 thr, warp tile 64x32,
// 2 CTA/SM. PW=20 (80B pitch: cp.async-aligned, conflict-free LDS).
// OM: 0 = fp32 out (+res), 2 = fp16 rows, 4 = fused QKV (q/k rows + v transposed).
#define STAGES 4
#define PW 20
#define STAGE_U32 (256*PW)
#define GEMM_SMEM (STAGES * STAGE_U32 * 4)

template<int OM, bool BIAS, bool RELU, bool RES>
__global__ void __launch_bounds__(256, 2) gemm_fp16(
    const __half* __restrict__ A, const __half* __restrict__ Bt,
    const float* __restrict__ bias, const float* __restrict__ res,
    float* __restrict__ C, __half* __restrict__ Ch,
    __half* __restrict__ Ch2, __half* __restrict__ Ch3,
    int M, int N, int K)
{
    extern __shared__ unsigned smg[];
    const int tid  = threadIdx.x;
    const int bm   = blockIdx.y * 128, bn = blockIdx.x * 128;
    const int warp = tid >> 5, lane = tid & 31;
    const int wm   = (warp >> 2) << 6;
    const int wn   = (warp & 3) << 5;
    const int g    = lane >> 2, q = lane & 3;

    const unsigned sbase = (unsigned)__cvta_generic_to_shared(smg);

    float acc[4][4][4];
    #pragma unroll
    for (int mi = 0; mi < 4; mi++)
        #pragma unroll
        for (int nj = 0; nj < 4; nj++)
            #pragma unroll
            for (int e = 0; e < 4; e++) acc[mi][nj][e] = 0.f;

    const int nt = K >> 5;

    #define G_ISSUE(buf, kt) do { \
        unsigned ab_ = sbase + (buf) * (STAGE_U32 * 4); \
        unsigned bb_ = ab_ + 128 * PW * 4; \
        _Pragma("unroll") \
        for (int i_ = 0; i_ < 2; i_++) { \
            int idx_ = tid + (i_ << 8); \
            int row_ = idx_ >> 2, seg_ = idx_ & 3; \
            cp16(ab_ + (row_ * PW + seg_ * 4) * 4, \
                 A  + (size_t)(bm + row_) * K + (kt) * 32 + seg_ * 8); \
            cp16(bb_ + (row_ * PW + seg_ * 4) * 4, \
                 Bt + (size_t)(bn + row_) * K + (kt) * 32 + seg_ * 8); \
        } \
    } while (0)

    #pragma unroll
    for (int s = 0; s < STAGES - 1; s++) {
        if (s < nt) G_ISSUE(s, s);
        CP_COMMIT();
    }

    for (int kt = 0; kt < nt; kt++) {
        CP_WAIT(STAGES - 2);
        __syncthreads();
        int nl = kt + STAGES - 1;
        if (nl < nt) G_ISSUE(nl % STAGES, nl);
        CP_COMMIT();

        const unsigned* Ab = smg + (kt % STAGES) * STAGE_U32;
        const unsigned* Bb = Ab + 128 * PW;
        #pragma unroll
        for (int ks = 0; ks < 2; ks++) {
            const int kw = ks << 3;
            unsigned af[4][4], bf[4][2];
            #pragma unroll
            for (int mi = 0; mi < 4; mi++) {
                int r = wm + (mi << 4) + g;
                af[mi][0] = Ab[r * PW + kw + q];
                af[mi][1] = Ab[(r + 8) * PW + kw + q];
                af[mi][2] = Ab[r * PW + kw + q + 4];
                af[mi][3] = Ab[(r + 8) * PW + kw + q + 4];
            }
            #pragma unroll
            for (int nj = 0; nj < 4; nj++) {
                int c = wn + (nj << 3) + g;
                bf[nj][0] = Bb[c * PW + kw + q];
                bf[nj][1] = Bb[c * PW + kw + q + 4];
            }
            #pragma unroll
            for (int mi = 0; mi < 4; mi++)
                #pragma unroll
                for (int nj = 0; nj < 4; nj++)
                    MMA_F16(acc[mi][nj], af[mi][0], af[mi][1], af[mi][2], af[mi][3],
                            bf[nj][0], bf[nj][1]);
        }
    }

    // epilogue
    #pragma unroll
    for (int mi = 0; mi < 4; mi++) {
        int r = bm + wm + (mi << 4) + g;
        #pragma unroll
        for (int nj = 0; nj < 4; nj++) {
            int c = bn + wn + (nj << 3) + (q << 1);
            float2 v0, v1;
            v0.x = acc[mi][nj][0]; v0.y = acc[mi][nj][1];
            v1.x = acc[mi][nj][2]; v1.y = acc[mi][nj][3];
            if (BIAS) {
                float2 bv = *reinterpret_cast<const float2*>(bias + c);
                v0.x += bv.x; v0.y += bv.y; v1.x += bv.x; v1.y += bv.y;
            }
            if (RELU) {
                v0.x = fmaxf(v0.x, 0.f); v0.y = fmaxf(v0.y, 0.f);
                v1.x = fmaxf(v1.x, 0.f); v1.y = fmaxf(v1.y, 0.f);
            }
            if (RES) {
                float2 r0 = *reinterpret_cast<const float2*>(res + (size_t)r * N + c);
                float2 r1 = *reinterpret_cast<const float2*>(res + (size_t)(r + 8) * N + c);
                v0.x += r0.x; v0.y += r0.y; v1.x += r1.x; v1.y += r1.y;
            }
            if (OM == 0) {
                *reinterpret_cast<float2*>(C + (size_t)r * N + c) = v0;
                *reinterpret_cast<float2*>(C + (size_t)(r + 8) * N + c) = v1;
            } else if (OM == 2) {
                *reinterpret_cast<__half2*>(Ch + (size_t)r * N + c) = __floats2half2_rn(v0.x, v0.y);
                *reinterpret_cast<__half2*>(Ch + (size_t)(r + 8) * N + c) = __floats2half2_rn(v1.x, v1.y);
            } else {  // OM == 4: fused QKV. regions aligned to 1024 (>> tile 128)
                if (bn < 1024) {
                    *reinterpret_cast<__half2*>(Ch + (size_t)r * DIMX + c) = __floats2half2_rn(v0.x, v0.y);
                    *reinterpret_cast<__half2*>(Ch + (size_t)(r + 8) * DIMX + c) = __floats2half2_rn(v1.x, v1.y);
                } else if (bn < 2048) {
                    int ck = c - 1024;
                    *reinterpret_cast<__half2*>(Ch2 + (size_t)r * DIMX + ck) = __floats2half2_rn(v0.x, v0.y);
                    *reinterpret_cast<__half2*>(Ch2 + (size_t)(r + 8) * DIMX + ck) = __floats2half2_rn(v1.x, v1.y);
                } else {
                    int cv = c - 2048;
                    Ch3[(size_t)cv * M + r]           = __float2half(v0.x);
                    Ch3[(size_t)(cv + 1) * M + r]     = __float2half(v0.y);
                    Ch3[(size_t)cv * M + r + 8]       = __float2half(v1.x);
                    Ch3[(size_t)(cv + 1) * M + r + 8] = __float2half(v1.y);
                }
            }
        }
    }
}

// ---------------- FP16 flash attention (m16n8k16, unchanged from rd12) --------
#define QST 36
#define ATT_SMEM ((128*QST + 2*64*QST + 2*64*QST) * 4)

__global__ void __launch_bounds__(256, 2) attn_tc(
    const __half* __restrict__ qb, const __half* __restrict__ kb,
    const __half* __restrict__ vT, __half* __restrict__ og)
{
    extern __shared__ unsigned sma[];
    unsigned* Qs = sma;
    unsigned* Ps = Qs;                      // alias

    const int tid  = threadIdx.x;
    const int warp = tid >> 5, lane = tid & 31;
    const int g    = lane >> 2, q4 = lane & 3;
    const int bh   = blockIdx.y;
    const int b    = bh >> 4, h = bh & 15;
    const int q0   = blockIdx.x * 128;
    const size_t rbase = (size_t)b * SSQ;
    const int r0 = warp << 4;
    const unsigned sbase = (unsigned)__cvta_generic_to_shared(sma);
    const unsigned ksb = sbase + 128 * QST * 4;
    const unsigned vsb = ksb + 2 * 64 * QST * 4;

    #pragma unroll
    for (int i = 0; i < 4; i++) {
        int f = tid + (i << 8);
        int row = f >> 3, seg = f & 7;
        cp16(sbase + (row * QST + seg * 4) * 4,
             qb + ((rbase + q0 + row) << 10) + (h << 6) + (seg << 3));
    }
    CP_COMMIT();

    #define A_ISSUE(buf, kt) do { \
        _Pragma("unroll") \
        for (int i_ = 0; i_ < 2; i_++) { \
            int f_ = tid + (i_ << 8); \
            int rr_ = f_ >> 3, sg_ = f_ & 7; \
            cp16(ksb + ((buf) * 64 * QST + rr_ * QST + sg_ * 4) * 4, \
                 kb + ((rbase + (kt) + rr_) << 10) + (h << 6) + (sg_ << 3)); \
            cp16(vsb + ((buf) * 64 * QST + rr_ * QST + sg_ * 4) * 4, \
                 vT + (size_t)((h << 6) + rr_) * MTOT + rbase + (kt) + (sg_ << 3)); \
        } \
    } while (0)

    CP_WAIT(0);
    __syncthreads();
    unsigned aq[4][4];
    #pragma unroll
    for (int ks = 0; ks < 4; ks++) {
        aq[ks][0] = Qs[(r0 + g) * QST + (ks << 3) + q4];
        aq[ks][1] = Qs[(r0 + 8 + g) * QST + (ks << 3) + q4];
        aq[ks][2] = Qs[(r0 + g) * QST + (ks << 3) + q4 + 4];
        aq[ks][3] = Qs[(r0 + 8 + g) * QST + (ks << 3) + q4 + 4];
    }

    A_ISSUE(0, 0);
    CP_COMMIT();

    float m0 = -1e30f, m1 = -1e30f, l0 = 0.f, l1 = 0.f;
    float oacc[8][4];
    #pragma unroll
    for (int j = 0; j < 8; j++)
        #pragma unroll
        for (int e = 0; e < 4; e++) oacc[j][e] = 0.f;

    const int NKT = SSQ / 64;
    for (int t = 0; t < NKT; t++) {
        __syncthreads();
        if (t + 1 < NKT) A_ISSUE((t + 1) & 1, (t + 1) * 64);
        CP_COMMIT();
        CP_WAIT(1);
        __syncthreads();

        const unsigned* Kb = sma + 128 * QST + (t & 1) * 64 * QST;
        const unsigned* Vb = sma + 128 * QST + 2 * 64 * QST + (t & 1) * 64 * QST;

        float s[8][4];
        #pragma unroll
        for (int j = 0; j < 8; j++)
            #pragma unroll
            for (int e = 0; e < 4; e++) s[j][e] = 0.f;
        #pragma unroll
        for (int ks = 0; ks < 4; ks++) {
            #pragma unroll
            for (int j = 0; j < 8; j++) {
                unsigned b0 = Kb[((j << 3) + g) * QST + (ks << 3) + q4];
                unsigned b1 = Kb[((j << 3) + g) * QST + (ks << 3) + q4 + 4];
                MMA_F16(s[j], aq[ks][0], aq[ks][1], aq[ks][2], aq[ks][3], b0, b1);
            }
        }

        float mt0 = -1e30f, mt1 = -1e30f;
        #pragma unroll
        for (int j = 0; j < 8; j++) {
            s[j][0] *= 0.125f; s[j][1] *= 0.125f; s[j][2] *= 0.125f; s[j][3] *= 0.125f;
            mt0 = fmaxf(mt0, fmaxf(s[j][0], s[j][1]));
            mt1 = fmaxf(mt1, fmaxf(s[j][2], s[j][3]));
        }
        mt0 = fmaxf(mt0, __shfl_xor_sync(0xffffffffu, mt0, 1));
        mt0 = fmaxf(mt0, __shfl_xor_sync(0xffffffffu, mt0, 2));
        mt1 = fmaxf(mt1, __shfl_xor_sync(0xffffffffu, mt1, 1));
        mt1 = fmaxf(mt1, __shfl_xor_sync(0xffffffffu, mt1, 2));
        float mn0 = fmaxf(m0, mt0), mn1 = fmaxf(m1, mt1);
        float corr0 = __expf(m0 - mn0), corr1 = __expf(m1 - mn1);
        m0 = mn0; m1 = mn1;
        float ls0 = 0.f, ls1 = 0.f;
        #pragma unroll
        for (int j = 0; j < 8; j++) {
            float p0 = __expf(s[j][0] - mn0);
            float p1 = __expf(s[j][1] - mn0);
            float p2 = __expf(s[j][2] - mn1);
            float p3 = __expf(s[j][3] - mn1);
            ls0 += p0 + p1; ls1 += p2 + p3;
            *reinterpret_cast<__half2*>(Ps + (r0 + g) * QST + (j << 2) + q4) =
                __floats2half2_rn(p0, p1);
            *reinterpret_cast<__half2*>(Ps + (r0 + 8 + g) * QST + (j << 2) + q4) =
                __floats2half2_rn(p2, p3);
        }
        ls0 += __shfl_xor_sync(0xffffffffu, ls0, 1);
        ls0 += __shfl_xor_sync(0xffffffffu, ls0, 2);
        ls1 += __shfl_xor_sync(0xffffffffu, ls1, 1);
        ls1 += __shfl_xor_sync(0xffffffffu, ls1, 2);
        l0 = l0 * corr0 + ls0;
        l1 = l1 * corr1 + ls1;
        #pragma unroll
        for (int j = 0; j < 8; j++) {
            oacc[j][0] *= corr0; oacc[j][1] *= corr0;
            oacc[j][2] *= corr1; oacc[j][3] *= corr1;
        }
        __syncwarp();

        #pragma unroll
        for (int ks = 0; ks < 4; ks++) {
            unsigned ap0 = Ps[(r0 + g) * QST + (ks << 3) + q4];
            unsigned ap1 = Ps[(r0 + 8 + g) * QST + (ks << 3) + q4];
            unsigned ap2 = Ps[(r0 + g) * QST + (ks << 3) + q4 + 4];
            unsigned ap3 = Ps[(r0 + 8 + g) * QST + (ks << 3) + q4 + 4];
            #pragma unroll
            for (int j = 0; j < 8; j++) {
                unsigned b0 = Vb[((j << 3) + g) * QST + (ks << 3) + q4];
                unsigned b1 = Vb[((j << 3) + g) * QST + (ks << 3) + q4 + 4];
                MMA_F16(oacc[j], ap0, ap1, ap2, ap3, b0, b1);
            }
        }
    }

    const size_t obase = rbase * DIMX + (size_t)h * HD;
    float il0 = 1.0f / l0, il1 = 1.0f / l1;
    #pragma unroll
    for (int j = 0; j < 8; j++) {
        size_t o0 = obase + (size_t)(q0 + r0 + g) * DIMX + (j << 3) + (q4 << 1);
        size_t o1 = obase + (size_t)(q0 + r0 + 8 + g) * DIMX + (j << 3) + (q4 << 1);
        *reinterpret_cast<__half2*>(og + o0) =
            __floats2half2_rn(oacc[j][0] * il0, oacc[j][1] * il0);
        *reinterpret_cast<__half2*>(og + o1) =
            __floats2half2_rn(oacc[j][2] * il1, oacc[j][3] * il1);
    }
}

// ---------------- launch ------------------------------------------------------
extern "C" void kernel_launch(void* const* d_in, const int* in_sizes, int n_in,
                              void* d_out, int out_size)
{
    const float* x    = (const float*)d_in[0];
    const float* wq   = (const float*)d_in[2];
    const float* wk   = (const float*)d_in[3];
    const float* wv   = (const float*)d_in[4];
    const float* wo   = (const float*)d_in[5];
    const float* w_up = (const float*)d_in[6];
    const float* b_up = (const float*)d_in[7];
    const float* w_dn = (const float*)d_in[8];
    const float* b_dn = (const float*)d_in[9];
    const float* l1a  = (const float*)d_in[10];
    const float* l1b  = (const float*)d_in[11];
    const float* l2a  = (const float*)d_in[12];
    const float* l2b  = (const float*)d_in[13];
    float* out = (float*)d_out;

    __half *h, *qb, *kb, *vT, *attn, *ffh, *wt;
    float *x2;
    {
        void* p;
        cudaGetSymbolAddress(&p, g_h);    h    = (__half*)p;
        cudaGetSymbolAddress(&p, g_q);    qb   = (__half*)p;
        cudaGetSymbolAddress(&p, g_k);    kb   = (__half*)p;
        cudaGetSymbolAddress(&p, g_v);    vT   = (__half*)p;
        cudaGetSymbolAddress(&p, g_attn); attn = (__half*)p;
        cudaGetSymbolAddress(&p, g_x2);   x2   = (float*)p;
        cudaGetSymbolAddress(&p, g_ffh);  ffh  = (__half*)p;
        cudaGetSymbolAddress(&p, g_wt);   wt   = (__half*)p;
    }

    __half* wqkv_t = wt;                       // [3072,1024] (contiguous q,k,v)
    __half* wo_t   = wt + 3 * 1024 * 1024;
    __half* wu_t   = wt + 4 * 1024 * 1024;
    __half* wd_t   = wt + 8 * 1024 * 1024;

    cudaFuncSetAttribute(gemm_fp16<4,false,false,false>, cudaFuncAttributeMaxDynamicSharedMemorySize, GEMM_SMEM);
    cudaFuncSetAttribute(gemm_fp16<0,false,false,true >, cudaFuncAttributeMaxDynamicSharedMemorySize, GEMM_SMEM);
    cudaFuncSetAttribute(gemm_fp16<2,true ,true ,false>, cudaFuncAttributeMaxDynamicSharedMemorySize, GEMM_SMEM);
    cudaFuncSetAttribute(gemm_fp16<0,true ,false,true >, cudaFuncAttributeMaxDynamicSharedMemorySize, GEMM_SMEM);
    cudaFuncSetAttribute(attn_tc, cudaFuncAttributeMaxDynamicSharedMemorySize, ATT_SMEM);

    dim3 thr(256);

    // 0: merged weight prep (single launch)
    prep_all_T<<<12288, thr>>>(wq, wk, wv, wo, w_up, w_dn, wt);

    // 1: h = LN1(x)  (fp16)
    ln_kernel<<<MTOT, thr>>>(x, l1a, l1b, h);

    // 2: fused QKV GEMM (q/k fp16 rows, v fp16 transposed)
    gemm_fp16<4,false,false,false><<<dim3(3072/128, MTOT/128), thr, GEMM_SMEM>>>(
        h, wqkv_t, nullptr, nullptr, nullptr, qb, kb, vT, MTOT, 3072, DIMX);

    // 3: attention -> attn (fp16 rows)
    attn_tc<<<dim3(SSQ/128, BB*NH), thr, ATT_SMEM>>>(qb, kb, vT, attn);

    // 4: x2 = x + attn @ wo  (fp32)
    gemm_fp16<0,false,false,true><<<dim3(DIMX/128, MTOT/128), thr, GEMM_SMEM>>>(
        attn, wo_t, nullptr, x, x2, nullptr, nullptr, nullptr, MTOT, DIMX, DIMX);

    // 5: h = LN2(x2)  (fp16)
    ln_kernel<<<MTOT, thr>>>(x2, l2a, l2b, h);

    // 6: ffh = relu(h @ w_up + b_up)  (fp16)
    gemm_fp16<2,true,true,false><<<dim3(DFF/128, MTOT/128), thr, GEMM_SMEM>>>(
        h, wu_t, b_up, nullptr, nullptr, ffh, nullptr, nullptr, MTOT, DFF, DIMX);

    // 7: out = x2 + ffh @ w_down + b_down  (fp32)
    gemm_fp16<0,true,false,true><<<dim3(DIMX/128, MTOT/128), thr, GEMM_SMEM>>>(
        ffh, wd_t, b_dn, x2, out, nullptr, nullptr, nullptr, MTOT, DIMX, DFF);
}

// round 14
// speedup vs baseline: 1.7745x; 1.0266x over previous
#include <cuda_runtime.h>
#include <cuda_fp16.h>
#include <math.h>

#define DIMX 1024
#define NH   16
#define HD   64
#define DFF  4096
#define BB   2
#define SSQ  2048
#define MTOT (BB*SSQ)
#define EPSV 1e-6f

// ---------------- scratch (device globals) ----------------------------------
__device__ __align__(256) __half g_h   [MTOT*DIMX];
__device__ __align__(256) __half g_q   [MTOT*DIMX];
__device__ __align__(256) __half g_k   [MTOT*DIMX];
__device__ __align__(256) __half g_v   [MTOT*DIMX];   // vT [1024][MTOT]
__device__ __align__(256) __half g_attn[MTOT*DIMX];
__device__ __align__(256) float  g_x2  [MTOT*DIMX];
__device__ __align__(256) __half g_ffh [MTOT*DFF];
__device__ __align__(256) __half g_wt  [12*1024*1024];  // transposed fp16 weights

// ---------------- helpers ----------------------------------------------------
__device__ __forceinline__ void cp16(unsigned s, const void* g) {
    asm volatile("cp.async.cg.shared.global [%0], [%1], 16;" :: "r"(s), "l"(g));
}
#define CP_COMMIT() asm volatile("cp.async.commit_group;")
#define CP_WAIT(n)  asm volatile("cp.async.wait_group %0;" :: "n"(n))

#define MMA_F16(c, a0, a1, a2, a3, b0, b1) asm volatile( \
    "mma.sync.aligned.m16n8k16.row.col.f32.f16.f16.f32 " \
    "{%0,%1,%2,%3}, {%4,%5,%6,%7}, {%8,%9}, {%0,%1,%2,%3};" \
    : "+f"((c)[0]), "+f"((c)[1]), "+f"((c)[2]), "+f"((c)[3]) \
    : "r"(a0), "r"(a1), "r"(a2), "r"(a3), "r"(b0), "r"(b1))

__device__ __forceinline__ unsigned packh2(float a, float b) {
    unsigned u;
    asm("cvt.rn.f16x2.f32 %0, %2, %1;" : "=r"(u) : "f"(a), "f"(b));
    return u;
}

// ---------------- merged weight prep (single launch) --------------------------
__global__ void __launch_bounds__(256) prep_all_T(
    const float* __restrict__ wq, const float* __restrict__ wk,
    const float* __restrict__ wv, const float* __restrict__ wo,
    const float* __restrict__ wu, const float* __restrict__ wd,
    __half* __restrict__ wt)
{
    __shared__ float t[32][33];
    int bid = blockIdx.x;
    const float* w; __half* o; int K, N, tile;
    if      (bid < 1024) { w = wq; o = wt;                 K = 1024; N = 1024; tile = bid; }
    else if (bid < 2048) { w = wk; o = wt + 1*1024*1024;   K = 1024; N = 1024; tile = bid - 1024; }
    else if (bid < 3072) { w = wv; o = wt + 2*1024*1024;   K = 1024; N = 1024; tile = bid - 2048; }
    else if (bid < 4096) { w = wo; o = wt + 3*1024*1024;   K = 1024; N = 1024; tile = bid - 3072; }
    else if (bid < 8192) { w = wu; o = wt + 4*1024*1024;   K = 1024; N = 4096; tile = bid - 4096; }
    else                 { w = wd; o = wt + 8*1024*1024;   K = 4096; N = 1024; tile = bid - 8192; }
    int ntN = N >> 5;
    int nb = (tile % ntN) << 5;
    int kt = (tile / ntN) << 5;
    int tid = threadIdx.x;
    #pragma unroll
    for (int i = 0; i < 4; i++) {
        int idx = tid + (i << 8);
        int r = idx >> 5, c = idx & 31;
        t[r][c] = w[(size_t)(kt + r) * N + nb + c];
    }
    __syncthreads();
    #pragma unroll
    for (int i = 0; i < 4; i++) {
        int idx = tid + (i << 8);
        int r = idx >> 5, c = idx & 31;
        o[(size_t)(nb + r) * K + kt + c] = __float2half(t[c][r]);
    }
}

// ---------------- LayerNorm (emits fp16) --------------------------------------
__global__ void __launch_bounds__(256) ln_kernel(
    const float* __restrict__ x, const float* __restrict__ alpha,
    const float* __restrict__ beta, __half* __restrict__ y)
{
    int row = blockIdx.x;
    int t = threadIdx.x;
    const float4* xr = reinterpret_cast<const float4*>(x + (size_t)row * DIMX);
    float4 v = xr[t];
    float s  = v.x + v.y + v.z + v.w;
    float sq = v.x*v.x + v.y*v.y + v.z*v.z + v.w*v.w;
    #pragma unroll
    for (int o = 16; o; o >>= 1) {
        s  += __shfl_xor_sync(0xffffffffu, s,  o);
        sq += __shfl_xor_sync(0xffffffffu, sq, o);
    }
    __shared__ float ss[8], ssq[8];
    int w = t >> 5, l = t & 31;
    if (l == 0) { ss[w] = s; ssq[w] = sq; }
    __syncthreads();
    if (w == 0) {
        s  = (l < 8) ? ss[l]  : 0.f;
        sq = (l < 8) ? ssq[l] : 0.f;
        #pragma unroll
        for (int o = 4; o; o >>= 1) {
            s  += __shfl_xor_sync(0xffffffffu, s,  o);
            sq += __shfl_xor_sync(0xffffffffu, sq, o);
        }
        if (l == 0) { ss[0] = s; ssq[0] = sq; }
    }
    __syncthreads();
    s = ss[0]; sq = ssq[0];
    float mu  = s * (1.0f / DIMX);
    float var = (sq - (float)DIMX * mu * mu) * (1.0f / (DIMX - 1));
    float sig = sqrtf(fmaxf(var, 0.f));
    float inv = 1.0f / (sig + EPSV);
    float4 a = reinterpret_cast<const float4*>(alpha)[t];
    float4 b = reinterpret_cast<const float4*>(beta)[t];
    __half2 h0 = __floats2half2_rn(a.x * (v.x - mu) * inv + b.x,
                                   a.y * (v.y - mu) * inv + b.y);
    __half2 h1 = __floats2half2_rn(a.z * (v.z - mu) * inv + b.z,
                                   a.w * (v.w - mu) * inv + b.w);
    size_t off = (size_t)row * DIMX + t * 4;
    reinterpret_cast<__half2*>(y + off)[0] = h0;
    reinterpret_cast<__half2*>(y + off)[1] = h1;
}

// ---------------- FP16 tensor GEMM (m16n8k16, 4-stage cp.async) ---------------
// OM: 0 = fp32 out (+res), 2 = fp16 rows, 4 = fused QKV (q scaled 1/8, k rows,
// v transposed).
#define STAGES 4
#define PW 20
#define STAGE_U32 (256*PW)
#define GEMM_SMEM (STAGES * STAGE_U32 * 4)

template<int OM, bool BIAS, bool RELU, bool RES>
__global__ void __launch_bounds__(256, 2) gemm_fp16(
    const __half* __restrict__ A, const __half* __restrict__ Bt,
    const float* __restrict__ bias, const float* __restrict__ res,
    float* __restrict__ C, __half* __restrict__ Ch,
    __half* __restrict__ Ch2, __half* __restrict__ Ch3,
    int M, int N, int K)
{
    extern __shared__ unsigned smg[];
    const int tid  = threadIdx.x;
    const int bm   = blockIdx.y * 128, bn = blockIdx.x * 128;
    const int warp = tid >> 5, lane = tid & 31;
    const int wm   = (warp >> 2) << 6;
    const int wn   = (warp & 3) << 5;
    const int g    = lane >> 2, q = lane & 3;

    const unsigned sbase = (unsigned)__cvta_generic_to_shared(smg);

    float acc[4][4][4];
    #pragma unroll
    for (int mi = 0; mi < 4; mi++)
        #pragma unroll
        for (int nj = 0; nj < 4; nj++)
            #pragma unroll
            for (int e = 0; e < 4; e++) acc[mi][nj][e] = 0.f;

    const int nt = K >> 5;

    #define G_ISSUE(buf, kt) do { \
        unsigned ab_ = sbase + (buf) * (STAGE_U32 * 4); \
        unsigned bb_ = ab_ + 128 * PW * 4; \
        _Pragma("unroll") \
        for (int i_ = 0; i_ < 2; i_++) { \
            int idx_ = tid + (i_ << 8); \
            int row_ = idx_ >> 2, seg_ = idx_ & 3; \
            cp16(ab_ + (row_ * PW + seg_ * 4) * 4, \
                 A  + (size_t)(bm + row_) * K + (kt) * 32 + seg_ * 8); \
            cp16(bb_ + (row_ * PW + seg_ * 4) * 4, \
                 Bt + (size_t)(bn + row_) * K + (kt) * 32 + seg_ * 8); \
        } \
    } while (0)

    #pragma unroll
    for (int s = 0; s < STAGES - 1; s++) {
        if (s < nt) G_ISSUE(s, s);
        CP_COMMIT();
    }

    for (int kt = 0; kt < nt; kt++) {
        CP_WAIT(STAGES - 2);
        __syncthreads();
        int nl = kt + STAGES - 1;
        if (nl < nt) G_ISSUE(nl % STAGES, nl);
        CP_COMMIT();

        const unsigned* Ab = smg + (kt % STAGES) * STAGE_U32;
        const unsigned* Bb = Ab + 128 * PW;
        #pragma unroll
        for (int ks = 0; ks < 2; ks++) {
            const int kw = ks << 3;
            unsigned af[4][4], bf[4][2];
            #pragma unroll
            for (int mi = 0; mi < 4; mi++) {
                int r = wm + (mi << 4) + g;
                af[mi][0] = Ab[r * PW + kw + q];
                af[mi][1] = Ab[(r + 8) * PW + kw + q];
                af[mi][2] = Ab[r * PW + kw + q + 4];
                af[mi][3] = Ab[(r + 8) * PW + kw + q + 4];
            }
            #pragma unroll
            for (int nj = 0; nj < 4; nj++) {
                int c = wn + (nj << 3) + g;
                bf[nj][0] = Bb[c * PW + kw + q];
                bf[nj][1] = Bb[c * PW + kw + q + 4];
            }
            #pragma unroll
            for (int mi = 0; mi < 4; mi++)
                #pragma unroll
                for (int nj = 0; nj < 4; nj++)
                    MMA_F16(acc[mi][nj], af[mi][0], af[mi][1], af[mi][2], af[mi][3],
                            bf[nj][0], bf[nj][1]);
        }
    }

    // epilogue
    #pragma unroll
    for (int mi = 0; mi < 4; mi++) {
        int r = bm + wm + (mi << 4) + g;
        #pragma unroll
        for (int nj = 0; nj < 4; nj++) {
            int c = bn + wn + (nj << 3) + (q << 1);
            float2 v0, v1;
            v0.x = acc[mi][nj][0]; v0.y = acc[mi][nj][1];
            v1.x = acc[mi][nj][2]; v1.y = acc[mi][nj][3];
            if (BIAS) {
                float2 bv = *reinterpret_cast<const float2*>(bias + c);
                v0.x += bv.x; v0.y += bv.y; v1.x += bv.x; v1.y += bv.y;
            }
            if (RELU) {
                v0.x = fmaxf(v0.x, 0.f); v0.y = fmaxf(v0.y, 0.f);
                v1.x = fmaxf(v1.x, 0.f); v1.y = fmaxf(v1.y, 0.f);
            }
            if (RES) {
                float2 r0 = *reinterpret_cast<const float2*>(res + (size_t)r * N + c);
                float2 r1 = *reinterpret_cast<const float2*>(res + (size_t)(r + 8) * N + c);
                v0.x += r0.x; v0.y += r0.y; v1.x += r1.x; v1.y += r1.y;
            }
            if (OM == 0) {
                *reinterpret_cast<float2*>(C + (size_t)r * N + c) = v0;
                *reinterpret_cast<float2*>(C + (size_t)(r + 8) * N + c) = v1;
            } else if (OM == 2) {
                *reinterpret_cast<__half2*>(Ch + (size_t)r * N + c) = __floats2half2_rn(v0.x, v0.y);
                *reinterpret_cast<__half2*>(Ch + (size_t)(r + 8) * N + c) = __floats2half2_rn(v1.x, v1.y);
            } else {  // OM == 4: fused QKV
                if (bn < 1024) {
                    // q region: fold 1/sqrt(HD) = 0.125 before fp16 round
                    *reinterpret_cast<__half2*>(Ch + (size_t)r * DIMX + c) =
                        __floats2half2_rn(v0.x * 0.125f, v0.y * 0.125f);
                    *reinterpret_cast<__half2*>(Ch + (size_t)(r + 8) * DIMX + c) =
                        __floats2half2_rn(v1.x * 0.125f, v1.y * 0.125f);
                } else if (bn < 2048) {
                    int ck = c - 1024;
                    *reinterpret_cast<__half2*>(Ch2 + (size_t)r * DIMX + ck) = __floats2half2_rn(v0.x, v0.y);
                    *reinterpret_cast<__half2*>(Ch2 + (size_t)(r + 8) * DIMX + ck) = __floats2half2_rn(v1.x, v1.y);
                } else {
                    int cv = c - 2048;
                    Ch3[(size_t)cv * M + r]           = __float2half(v0.x);
                    Ch3[(size_t)(cv + 1) * M + r]     = __float2half(v0.y);
                    Ch3[(size_t)cv * M + r + 8]       = __float2half(v1.x);
                    Ch3[(size_t)(cv + 1) * M + r + 8] = __float2half(v1.y);
                }
            }
        }
    }
}

// ---------------- FP16 flash attention: register-resident P -------------------
// q pre-scaled by 0.125. S C-frags repacked directly into PV A-frags (no smem
// P roundtrip, no syncwarp).
#define QST 36
#define ATT_SMEM ((128*QST + 2*64*QST + 2*64*QST) * 4)

__global__ void __launch_bounds__(256, 2) attn_tc(
    const __half* __restrict__ qb, const __half* __restrict__ kb,
    const __half* __restrict__ vT, __half* __restrict__ og)
{
    extern __shared__ unsigned sma[];
    unsigned* Qs = sma;

    const int tid  = threadIdx.x;
    const int warp = tid >> 5, lane = tid & 31;
    const int g    = lane >> 2, q4 = lane & 3;
    const int bh   = blockIdx.y;
    const int b    = bh >> 4, h = bh & 15;
    const int q0   = blockIdx.x * 128;
    const size_t rbase = (size_t)b * SSQ;
    const int r0 = warp << 4;
    const unsigned sbase = (unsigned)__cvta_generic_to_shared(sma);
    const unsigned ksb = sbase + 128 * QST * 4;
    const unsigned vsb = ksb + 2 * 64 * QST * 4;

    #pragma unroll
    for (int i = 0; i < 4; i++) {
        int f = tid + (i << 8);
        int row = f >> 3, seg = f & 7;
        cp16(sbase + (row * QST + seg * 4) * 4,
             qb + ((rbase + q0 + row) << 10) + (h << 6) + (seg << 3));
    }
    CP_COMMIT();

    #define A_ISSUE(buf, kt) do { \
        _Pragma("unroll") \
        for (int i_ = 0; i_ < 2; i_++) { \
            int f_ = tid + (i_ << 8); \
            int rr_ = f_ >> 3, sg_ = f_ & 7; \
            cp16(ksb + ((buf) * 64 * QST + rr_ * QST + sg_ * 4) * 4, \
                 kb + ((rbase + (kt) + rr_) << 10) + (h << 6) + (sg_ << 3)); \
            cp16(vsb + ((buf) * 64 * QST + rr_ * QST + sg_ * 4) * 4, \
                 vT + (size_t)((h << 6) + rr_) * MTOT + rbase + (kt) + (sg_ << 3)); \
        } \
    } while (0)

    CP_WAIT(0);
    __syncthreads();
    unsigned aq[4][4];
    #pragma unroll
    for (int ks = 0; ks < 4; ks++) {
        aq[ks][0] = Qs[(r0 + g) * QST + (ks << 3) + q4];
        aq[ks][1] = Qs[(r0 + 8 + g) * QST + (ks << 3) + q4];
        aq[ks][2] = Qs[(r0 + g) * QST + (ks << 3) + q4 + 4];
        aq[ks][3] = Qs[(r0 + 8 + g) * QST + (ks << 3) + q4 + 4];
    }

    A_ISSUE(0, 0);
    CP_COMMIT();

    float m0 = -1e30f, m1 = -1e30f, l0 = 0.f, l1 = 0.f;
    float oacc[8][4];
    #pragma unroll
    for (int j = 0; j < 8; j++)
        #pragma unroll
        for (int e = 0; e < 4; e++) oacc[j][e] = 0.f;

    const int NKT = SSQ / 64;
    for (int t = 0; t < NKT; t++) {
        __syncthreads();
        if (t + 1 < NKT) A_ISSUE((t + 1) & 1, (t + 1) * 64);
        CP_COMMIT();
        CP_WAIT(1);
        __syncthreads();

        const unsigned* Kb = sma + 128 * QST + (t & 1) * 64 * QST;
        const unsigned* Vb = sma + 128 * QST + 2 * 64 * QST + (t & 1) * 64 * QST;

        // S = Q K^T  (q pre-scaled)
        float s[8][4];
        #pragma unroll
        for (int j = 0; j < 8; j++)
            #pragma unroll
            for (int e = 0; e < 4; e++) s[j][e] = 0.f;
        #pragma unroll
        for (int ks = 0; ks < 4; ks++) {
            #pragma unroll
            for (int j = 0; j < 8; j++) {
                unsigned b0 = Kb[((j << 3) + g) * QST + (ks << 3) + q4];
                unsigned b1 = Kb[((j << 3) + g) * QST + (ks << 3) + q4 + 4];
                MMA_F16(s[j], aq[ks][0], aq[ks][1], aq[ks][2], aq[ks][3], b0, b1);
            }
        }

        // online softmax (fp32); p values stay in s[][]
        float mt0 = -1e30f, mt1 = -1e30f;
        #pragma unroll
        for (int j = 0; j < 8; j++) {
            mt0 = fmaxf(mt0, fmaxf(s[j][0], s[j][1]));
            mt1 = fmaxf(mt1, fmaxf(s[j][2], s[j][3]));
        }
        mt0 = fmaxf(mt0, __shfl_xor_sync(0xffffffffu, mt0, 1));
        mt0 = fmaxf(mt0, __shfl_xor_sync(0xffffffffu, mt0, 2));
        mt1 = fmaxf(mt1, __shfl_xor_sync(0xffffffffu, mt1, 1));
        mt1 = fmaxf(mt1, __shfl_xor_sync(0xffffffffu, mt1, 2));
        float mn0 = fmaxf(m0, mt0), mn1 = fmaxf(m1, mt1);
        float corr0 = __expf(m0 - mn0), corr1 = __expf(m1 - mn1);
        m0 = mn0; m1 = mn1;
        float ls0 = 0.f, ls1 = 0.f;
        #pragma unroll
        for (int j = 0; j < 8; j++) {
            s[j][0] = __expf(s[j][0] - mn0);
            s[j][1] = __expf(s[j][1] - mn0);
            s[j][2] = __expf(s[j][2] - mn1);
            s[j][3] = __expf(s[j][3] - mn1);
            ls0 += s[j][0] + s[j][1];
            ls1 += s[j][2] + s[j][3];
        }
        ls0 += __shfl_xor_sync(0xffffffffu, ls0, 1);
        ls0 += __shfl_xor_sync(0xffffffffu, ls0, 2);
        ls1 += __shfl_xor_sync(0xffffffffu, ls1, 1);
        ls1 += __shfl_xor_sync(0xffffffffu, ls1, 2);
        l0 = l0 * corr0 + ls0;
        l1 = l1 * corr1 + ls1;
        #pragma unroll
        for (int j = 0; j < 8; j++) {
            oacc[j][0] *= corr0; oacc[j][1] *= corr0;
            oacc[j][2] *= corr1; oacc[j][3] *= corr1;
        }

        // O += P @ V  — P fragments packed directly from S fragments
        #pragma unroll
        for (int ks = 0; ks < 4; ks++) {
            unsigned ap0 = packh2(s[2*ks][0],     s[2*ks][1]);
            unsigned ap1 = packh2(s[2*ks][2],     s[2*ks][3]);
            unsigned ap2 = packh2(s[2*ks + 1][0], s[2*ks + 1][1]);
            unsigned ap3 = packh2(s[2*ks + 1][2], s[2*ks + 1][3]);
            #pragma unroll
            for (int j = 0; j < 8; j++) {
                unsigned b0 = Vb[((j << 3) + g) * QST + (ks << 3) + q4];
                unsigned b1 = Vb[((j << 3) + g) * QST + (ks << 3) + q4 + 4];
                MMA_F16(oacc[j], ap0, ap1, ap2, ap3, b0, b1);
            }
        }
    }

    const size_t obase = rbase * DIMX + (size_t)h * HD;
    float il0 = 1.0f / l0, il1 = 1.0f / l1;
    #pragma unroll
    for (int j = 0; j < 8; j++) {
        size_t o0 = obase + (size_t)(q0 + r0 + g) * DIMX + (j << 3) + (q4 << 1);
        size_t o1 = obase + (size_t)(q0 + r0 + 8 + g) * DIMX + (j << 3) + (q4 << 1);
        *reinterpret_cast<__half2*>(og + o0) =
            __floats2half2_rn(oacc[j][0] * il0, oacc[j][1] * il0);
        *reinterpret_cast<__half2*>(og + o1) =
            __floats2half2_rn(oacc[j][2] * il1, oacc[j][3] * il1);
    }
}

// ---------------- launch ------------------------------------------------------
extern "C" void kernel_launch(void* const* d_in, const int* in_sizes, int n_in,
                              void* d_out, int out_size)
{
    const float* x    = (const float*)d_in[0];
    const float* wq   = (const float*)d_in[2];
    const float* wk   = (const float*)d_in[3];
    const float* wv   = (const float*)d_in[4];
    const float* wo   = (const float*)d_in[5];
    const float* w_up = (const float*)d_in[6];
    const float* b_up = (const float*)d_in[7];
    const float* w_dn = (const float*)d_in[8];
    const float* b_dn = (const float*)d_in[9];
    const float* l1a  = (const float*)d_in[10];
    const float* l1b  = (const float*)d_in[11];
    const float* l2a  = (const float*)d_in[12];
    const float* l2b  = (const float*)d_in[13];
    float* out = (float*)d_out;

    __half *h, *qb, *kb, *vT, *attn, *ffh, *wt;
    float *x2;
    {
        void* p;
        cudaGetSymbolAddress(&p, g_h);    h    = (__half*)p;
        cudaGetSymbolAddress(&p, g_q);    qb   = (__half*)p;
        cudaGetSymbolAddress(&p, g_k);    kb   = (__half*)p;
        cudaGetSymbolAddress(&p, g_v);    vT   = (__half*)p;
        cudaGetSymbolAddress(&p, g_attn); attn = (__half*)p;
        cudaGetSymbolAddress(&p, g_x2);   x2   = (float*)p;
        cudaGetSymbolAddress(&p, g_ffh);  ffh  = (__half*)p;
        cudaGetSymbolAddress(&p, g_wt);   wt   = (__half*)p;
    }

    __half* wqkv_t = wt;
    __half* wo_t   = wt + 3 * 1024 * 1024;
    __half* wu_t   = wt + 4 * 1024 * 1024;
    __half* wd_t   = wt + 8 * 1024 * 1024;

    cudaFuncSetAttribute(gemm_fp16<4,false,false,false>, cudaFuncAttributeMaxDynamicSharedMemorySize, GEMM_SMEM);
    cudaFuncSetAttribute(gemm_fp16<0,false,false,true >, cudaFuncAttributeMaxDynamicSharedMemorySize, GEMM_SMEM);
    cudaFuncSetAttribute(gemm_fp16<2,true ,true ,false>, cudaFuncAttributeMaxDynamicSharedMemorySize, GEMM_SMEM);
    cudaFuncSetAttribute(gemm_fp16<0,true ,false,true >, cudaFuncAttributeMaxDynamicSharedMemorySize, GEMM_SMEM);
    cudaFuncSetAttribute(attn_tc, cudaFuncAttributeMaxDynamicSharedMemorySize, ATT_SMEM);

    dim3 thr(256);

    prep_all_T<<<12288, thr>>>(wq, wk, wv, wo, w_up, w_dn, wt);

    ln_kernel<<<MTOT, thr>>>(x, l1a, l1b, h);

    gemm_fp16<4,false,false,false><<<dim3(3072/128, MTOT/128), thr, GEMM_SMEM>>>(
        h, wqkv_t, nullptr, nullptr, nullptr, qb, kb, vT, MTOT, 3072, DIMX);

    attn_tc<<<dim3(SSQ/128, BB*NH), thr, ATT_SMEM>>>(qb, kb, vT, attn);

    gemm_fp16<0,false,false,true><<<dim3(DIMX/128, MTOT/128), thr, GEMM_SMEM>>>(
        attn, wo_t, nullptr, x, x2, nullptr, nullptr, nullptr, MTOT, DIMX, DIMX);

    ln_kernel<<<MTOT, thr>>>(x2, l2a, l2b, h);

    gemm_fp16<2,true,true,false><<<dim3(DFF/128, MTOT/128), thr, GEMM_SMEM>>>(
        h, wu_t, b_up, nullptr, nullptr, ffh, nullptr, nullptr, MTOT, DFF, DIMX);

    gemm_fp16<0,true,false,true><<<dim3(DIMX/128, MTOT/128), thr, GEMM_SMEM>>>(
        ffh, wd_t, b_dn, x2, out, nullptr, nullptr, nullptr, MTOT, DIMX, DFF);
}

// round 15
// speedup vs baseline: 1.8174x; 1.0242x over previous
#include <cuda_runtime.h>
#include <cuda_fp16.h>
#include <math.h>

#define DIMX 1024
#define NH   16
#define HD   64
#define DFF  4096
#define BB   2
#define SSQ  2048
#define MTOT (BB*SSQ)
#define EPSV 1e-6f

// ---------------- scratch (device globals) ----------------------------------
__device__ __align__(256) __half g_h   [MTOT*DIMX];
__device__ __align__(256) __half g_q   [MTOT*DIMX];
__device__ __align__(256) __half g_k   [MTOT*DIMX];
__device__ __align__(256) __half g_v   [MTOT*DIMX];   // vT [1024][MTOT]
__device__ __align__(256) __half g_attn[MTOT*DIMX];
__device__ __align__(256) float  g_x2  [MTOT*DIMX];
__device__ __align__(256) __half g_ffh [MTOT*DFF];
__device__ __align__(256) __half g_wt  [12*1024*1024];  // transposed fp16 weights

// ---------------- helpers ----------------------------------------------------
__device__ __forceinline__ void cp16(unsigned s, const void* g) {
    asm volatile("cp.async.cg.shared.global [%0], [%1], 16;" :: "r"(s), "l"(g));
}
#define CP_COMMIT() asm volatile("cp.async.commit_group;")
#define CP_WAIT(n)  asm volatile("cp.async.wait_group %0;" :: "n"(n))

#define MMA_F16(c, a0, a1, a2, a3, b0, b1) asm volatile( \
    "mma.sync.aligned.m16n8k16.row.col.f32.f16.f16.f32 " \
    "{%0,%1,%2,%3}, {%4,%5,%6,%7}, {%8,%9}, {%0,%1,%2,%3};" \
    : "+f"((c)[0]), "+f"((c)[1]), "+f"((c)[2]), "+f"((c)[3]) \
    : "r"(a0), "r"(a1), "r"(a2), "r"(a3), "r"(b0), "r"(b1))

#define LDSM4(r, a) asm volatile( \
    "ldmatrix.sync.aligned.m8n8.x4.shared.b16 {%0,%1,%2,%3}, [%4];" \
    : "=r"((r)[0]), "=r"((r)[1]), "=r"((r)[2]), "=r"((r)[3]) : "r"(a))

__device__ __forceinline__ unsigned packh2(float a, float b) {
    unsigned u;
    asm("cvt.rn.f16x2.f32 %0, %2, %1;" : "=r"(u) : "f"(a), "f"(b));
    return u;
}
__device__ __forceinline__ unsigned ex2h2(unsigned a) {
    unsigned u;
    asm("ex2.approx.f16x2 %0, %1;" : "=r"(u) : "r"(a));
    return u;
}

// ---------------- merged weight prep (single launch) --------------------------
__global__ void __launch_bounds__(256) prep_all_T(
    const float* __restrict__ wq, const float* __restrict__ wk,
    const float* __restrict__ wv, const float* __restrict__ wo,
    const float* __restrict__ wu, const float* __restrict__ wd,
    __half* __restrict__ wt)
{
    __shared__ float t[32][33];
    int bid = blockIdx.x;
    const float* w; __half* o; int K, N, tile;
    if      (bid < 1024) { w = wq; o = wt;                 K = 1024; N = 1024; tile = bid; }
    else if (bid < 2048) { w = wk; o = wt + 1*1024*1024;   K = 1024; N = 1024; tile = bid - 1024; }
    else if (bid < 3072) { w = wv; o = wt + 2*1024*1024;   K = 1024; N = 1024; tile = bid - 2048; }
    else if (bid < 4096) { w = wo; o = wt + 3*1024*1024;   K = 1024; N = 1024; tile = bid - 3072; }
    else if (bid < 8192) { w = wu; o = wt + 4*1024*1024;   K = 1024; N = 4096; tile = bid - 4096; }
    else                 { w = wd; o = wt + 8*1024*1024;   K = 4096; N = 1024; tile = bid - 8192; }
    int ntN = N >> 5;
    int nb = (tile % ntN) << 5;
    int kt = (tile / ntN) << 5;
    int tid = threadIdx.x;
    #pragma unroll
    for (int i = 0; i < 4; i++) {
        int idx = tid + (i << 8);
        int r = idx >> 5, c = idx & 31;
        t[r][c] = w[(size_t)(kt + r) * N + nb + c];
    }
    __syncthreads();
    #pragma unroll
    for (int i = 0; i < 4; i++) {
        int idx = tid + (i << 8);
        int r = idx >> 5, c = idx & 31;
        o[(size_t)(nb + r) * K + kt + c] = __float2half(t[c][r]);
    }
}

// ---------------- LayerNorm (emits fp16) --------------------------------------
__global__ void __launch_bounds__(256) ln_kernel(
    const float* __restrict__ x, const float* __restrict__ alpha,
    const float* __restrict__ beta, __half* __restrict__ y)
{
    int row = blockIdx.x;
    int t = threadIdx.x;
    const float4* xr = reinterpret_cast<const float4*>(x + (size_t)row * DIMX);
    float4 v = xr[t];
    float s  = v.x + v.y + v.z + v.w;
    float sq = v.x*v.x + v.y*v.y + v.z*v.z + v.w*v.w;
    #pragma unroll
    for (int o = 16; o; o >>= 1) {
        s  += __shfl_xor_sync(0xffffffffu, s,  o);
        sq += __shfl_xor_sync(0xffffffffu, sq, o);
    }
    __shared__ float ss[8], ssq[8];
    int w = t >> 5, l = t & 31;
    if (l == 0) { ss[w] = s; ssq[w] = sq; }
    __syncthreads();
    if (w == 0) {
        s  = (l < 8) ? ss[l]  : 0.f;
        sq = (l < 8) ? ssq[l] : 0.f;
        #pragma unroll
        for (int o = 4; o; o >>= 1) {
            s  += __shfl_xor_sync(0xffffffffu, s,  o);
            sq += __shfl_xor_sync(0xffffffffu, sq, o);
        }
        if (l == 0) { ss[0] = s; ssq[0] = sq; }
    }
    __syncthreads();
    s = ss[0]; sq = ssq[0];
    float mu  = s * (1.0f / DIMX);
    float var = (sq - (float)DIMX * mu * mu) * (1.0f / (DIMX - 1));
    float sig = sqrtf(fmaxf(var, 0.f));
    float inv = 1.0f / (sig + EPSV);
    float4 a = reinterpret_cast<const float4*>(alpha)[t];
    float4 b = reinterpret_cast<const float4*>(beta)[t];
    __half2 h0 = __floats2half2_rn(a.x * (v.x - mu) * inv + b.x,
                                   a.y * (v.y - mu) * inv + b.y);
    __half2 h1 = __floats2half2_rn(a.z * (v.z - mu) * inv + b.z,
                                   a.w * (v.w - mu) * inv + b.w);
    size_t off = (size_t)row * DIMX + t * 4;
    reinterpret_cast<__half2*>(y + off)[0] = h0;
    reinterpret_cast<__half2*>(y + off)[1] = h1;
}

// ---------------- FP16 tensor GEMM (m16n8k16, 4-stage cp.async) ---------------
// OM: 0 = fp32 out (+res), 2 = fp16 rows, 4 = fused QKV (q scaled 1/8, k rows,
// v transposed).
#define STAGES 4
#define PW 20
#define STAGE_U32 (256*PW)
#define GEMM_SMEM (STAGES * STAGE_U32 * 4)

template<int OM, bool BIAS, bool RELU, bool RES>
__global__ void __launch_bounds__(256, 2) gemm_fp16(
    const __half* __restrict__ A, const __half* __restrict__ Bt,
    const float* __restrict__ bias, const float* __restrict__ res,
    float* __restrict__ C, __half* __restrict__ Ch,
    __half* __restrict__ Ch2, __half* __restrict__ Ch3,
    int M, int N, int K)
{
    extern __shared__ unsigned smg[];
    const int tid  = threadIdx.x;
    const int bm   = blockIdx.y * 128, bn = blockIdx.x * 128;
    const int warp = tid >> 5, lane = tid & 31;
    const int wm   = (warp >> 2) << 6;
    const int wn   = (warp & 3) << 5;
    const int g    = lane >> 2, q = lane & 3;

    const unsigned sbase = (unsigned)__cvta_generic_to_shared(smg);

    float acc[4][4][4];
    #pragma unroll
    for (int mi = 0; mi < 4; mi++)
        #pragma unroll
        for (int nj = 0; nj < 4; nj++)
            #pragma unroll
            for (int e = 0; e < 4; e++) acc[mi][nj][e] = 0.f;

    const int nt = K >> 5;

    #define G_ISSUE(buf, kt) do { \
        unsigned ab_ = sbase + (buf) * (STAGE_U32 * 4); \
        unsigned bb_ = ab_ + 128 * PW * 4; \
        _Pragma("unroll") \
        for (int i_ = 0; i_ < 2; i_++) { \
            int idx_ = tid + (i_ << 8); \
            int row_ = idx_ >> 2, seg_ = idx_ & 3; \
            cp16(ab_ + (row_ * PW + seg_ * 4) * 4, \
                 A  + (size_t)(bm + row_) * K + (kt) * 32 + seg_ * 8); \
            cp16(bb_ + (row_ * PW + seg_ * 4) * 4, \
                 Bt + (size_t)(bn + row_) * K + (kt) * 32 + seg_ * 8); \
        } \
    } while (0)

    #pragma unroll
    for (int s = 0; s < STAGES - 1; s++) {
        if (s < nt) G_ISSUE(s, s);
        CP_COMMIT();
    }

    for (int kt = 0; kt < nt; kt++) {
        CP_WAIT(STAGES - 2);
        __syncthreads();
        int nl = kt + STAGES - 1;
        if (nl < nt) G_ISSUE(nl % STAGES, nl);
        CP_COMMIT();

        const unsigned* Ab = smg + (kt % STAGES) * STAGE_U32;
        const unsigned* Bb = Ab + 128 * PW;
        #pragma unroll
        for (int ks = 0; ks < 2; ks++) {
            const int kw = ks << 3;
            unsigned af[4][4], bf[4][2];
            #pragma unroll
            for (int mi = 0; mi < 4; mi++) {
                int r = wm + (mi << 4) + g;
                af[mi][0] = Ab[r * PW + kw + q];
                af[mi][1] = Ab[(r + 8) * PW + kw + q];
                af[mi][2] = Ab[r * PW + kw + q + 4];
                af[mi][3] = Ab[(r + 8) * PW + kw + q + 4];
            }
            #pragma unroll
            for (int nj = 0; nj < 4; nj++) {
                int c = wn + (nj << 3) + g;
                bf[nj][0] = Bb[c * PW + kw + q];
                bf[nj][1] = Bb[c * PW + kw + q + 4];
            }
            #pragma unroll
            for (int mi = 0; mi < 4; mi++)
                #pragma unroll
                for (int nj = 0; nj < 4; nj++)
                    MMA_F16(acc[mi][nj], af[mi][0], af[mi][1], af[mi][2], af[mi][3],
                            bf[nj][0], bf[nj][1]);
        }
    }

    // epilogue
    #pragma unroll
    for (int mi = 0; mi < 4; mi++) {
        int r = bm + wm + (mi << 4) + g;
        #pragma unroll
        for (int nj = 0; nj < 4; nj++) {
            int c = bn + wn + (nj << 3) + (q << 1);
            float2 v0, v1;
            v0.x = acc[mi][nj][0]; v0.y = acc[mi][nj][1];
            v1.x = acc[mi][nj][2]; v1.y = acc[mi][nj][3];
            if (BIAS) {
                float2 bv = *reinterpret_cast<const float2*>(bias + c);
                v0.x += bv.x; v0.y += bv.y; v1.x += bv.x; v1.y += bv.y;
            }
            if (RELU) {
                v0.x = fmaxf(v0.x, 0.f); v0.y = fmaxf(v0.y, 0.f);
                v1.x = fmaxf(v1.x, 0.f); v1.y = fmaxf(v1.y, 0.f);
            }
            if (RES) {
                float2 r0 = *reinterpret_cast<const float2*>(res + (size_t)r * N + c);
                float2 r1 = *reinterpret_cast<const float2*>(res + (size_t)(r + 8) * N + c);
                v0.x += r0.x; v0.y += r0.y; v1.x += r1.x; v1.y += r1.y;
            }
            if (OM == 0) {
                *reinterpret_cast<float2*>(C + (size_t)r * N + c) = v0;
                *reinterpret_cast<float2*>(C + (size_t)(r + 8) * N + c) = v1;
            } else if (OM == 2) {
                *reinterpret_cast<__half2*>(Ch + (size_t)r * N + c) = __floats2half2_rn(v0.x, v0.y);
                *reinterpret_cast<__half2*>(Ch + (size_t)(r + 8) * N + c) = __floats2half2_rn(v1.x, v1.y);
            } else {  // OM == 4: fused QKV
                if (bn < 1024) {
                    *reinterpret_cast<__half2*>(Ch + (size_t)r * DIMX + c) =
                        __floats2half2_rn(v0.x * 0.125f, v0.y * 0.125f);
                    *reinterpret_cast<__half2*>(Ch + (size_t)(r + 8) * DIMX + c) =
                        __floats2half2_rn(v1.x * 0.125f, v1.y * 0.125f);
                } else if (bn < 2048) {
                    int ck = c - 1024;
                    *reinterpret_cast<__half2*>(Ch2 + (size_t)r * DIMX + ck) = __floats2half2_rn(v0.x, v0.y);
                    *reinterpret_cast<__half2*>(Ch2 + (size_t)(r + 8) * DIMX + ck) = __floats2half2_rn(v1.x, v1.y);
                } else {
                    int cv = c - 2048;
                    Ch3[(size_t)cv * M + r]           = __float2half(v0.x);
                    Ch3[(size_t)(cv + 1) * M + r]     = __float2half(v0.y);
                    Ch3[(size_t)cv * M + r + 8]       = __float2half(v1.x);
                    Ch3[(size_t)(cv + 1) * M + r + 8] = __float2half(v1.y);
                }
            }
        }
    }
}

// ---------------- FP16 flash attention: ldmatrix + f16x2 exp -------------------
#define QST 36
#define ATT_SMEM ((128*QST + 2*64*QST + 2*64*QST) * 4)

__global__ void __launch_bounds__(256, 2) attn_tc(
    const __half* __restrict__ qb, const __half* __restrict__ kb,
    const __half* __restrict__ vT, __half* __restrict__ og)
{
    extern __shared__ unsigned sma[];
    unsigned* Qs = sma;

    const int tid  = threadIdx.x;
    const int warp = tid >> 5, lane = tid & 31;
    const int g    = lane >> 2, q4 = lane & 3;
    const int lr   = (lane & 7) + ((lane >> 3) & 1) * 8;
    const int lc   = (lane >> 4) * 4;
    const int bh   = blockIdx.y;
    const int b    = bh >> 4, h = bh & 15;
    const int q0   = blockIdx.x * 128;
    const size_t rbase = (size_t)b * SSQ;
    const int r0 = warp << 4;
    const unsigned sbase = (unsigned)__cvta_generic_to_shared(sma);
    const unsigned ksb = sbase + 128 * QST * 4;
    const unsigned vsb = ksb + 2 * 64 * QST * 4;

    #pragma unroll
    for (int i = 0; i < 4; i++) {
        int f = tid + (i << 8);
        int row = f >> 3, seg = f & 7;
        cp16(sbase + (row * QST + seg * 4) * 4,
             qb + ((rbase + q0 + row) << 10) + (h << 6) + (seg << 3));
    }
    CP_COMMIT();

    #define A_ISSUE(buf, kt) do { \
        _Pragma("unroll") \
        for (int i_ = 0; i_ < 2; i_++) { \
            int f_ = tid + (i_ << 8); \
            int rr_ = f_ >> 3, sg_ = f_ & 7; \
            cp16(ksb + ((buf) * 64 * QST + rr_ * QST + sg_ * 4) * 4, \
                 kb + ((rbase + (kt) + rr_) << 10) + (h << 6) + (sg_ << 3)); \
            cp16(vsb + ((buf) * 64 * QST + rr_ * QST + sg_ * 4) * 4, \
                 vT + (size_t)((h << 6) + rr_) * MTOT + rbase + (kt) + (sg_ << 3)); \
        } \
    } while (0)

    CP_WAIT(0);
    __syncthreads();
    unsigned aq[4][4];
    #pragma unroll
    for (int ks = 0; ks < 4; ks++) {
        aq[ks][0] = Qs[(r0 + g) * QST + (ks << 3) + q4];
        aq[ks][1] = Qs[(r0 + 8 + g) * QST + (ks << 3) + q4];
        aq[ks][2] = Qs[(r0 + g) * QST + (ks << 3) + q4 + 4];
        aq[ks][3] = Qs[(r0 + 8 + g) * QST + (ks << 3) + q4 + 4];
    }

    A_ISSUE(0, 0);
    CP_COMMIT();

    float m0 = -1e30f, m1 = -1e30f, l0 = 0.f, l1 = 0.f;
    float oacc[8][4];
    #pragma unroll
    for (int j = 0; j < 8; j++)
        #pragma unroll
        for (int e = 0; e < 4; e++) oacc[j][e] = 0.f;

    const float L2E = 1.4426950408889634f;
    const int NKT = SSQ / 64;
    for (int t = 0; t < NKT; t++) {
        __syncthreads();
        if (t + 1 < NKT) A_ISSUE((t + 1) & 1, (t + 1) * 64);
        CP_COMMIT();
        CP_WAIT(1);
        __syncthreads();

        const unsigned kbb = ksb + (t & 1) * 64 * QST * 4;
        const unsigned vbb = vsb + (t & 1) * 64 * QST * 4;

        // S = Q K^T  (K fragments via ldmatrix.x4)
        float s[8][4];
        #pragma unroll
        for (int j = 0; j < 8; j++)
            #pragma unroll
            for (int e = 0; e < 4; e++) s[j][e] = 0.f;
        #pragma unroll
        for (int ks = 0; ks < 4; ks++) {
            const int kw = ks << 3;
            #pragma unroll
            for (int p = 0; p < 4; p++) {
                unsigned bk[4];
                LDSM4(bk, kbb + ((((p << 4) + lr) * QST) + kw + lc) * 4);
                MMA_F16(s[2*p],     aq[ks][0], aq[ks][1], aq[ks][2], aq[ks][3], bk[0], bk[2]);
                MMA_F16(s[2*p + 1], aq[ks][0], aq[ks][1], aq[ks][2], aq[ks][3], bk[1], bk[3]);
            }
        }

        // online softmax (max in fp32, exp via ex2.approx.f16x2)
        float mt0 = -1e30f, mt1 = -1e30f;
        #pragma unroll
        for (int j = 0; j < 8; j++) {
            mt0 = fmaxf(mt0, fmaxf(s[j][0], s[j][1]));
            mt1 = fmaxf(mt1, fmaxf(s[j][2], s[j][3]));
        }
        mt0 = fmaxf(mt0, __shfl_xor_sync(0xffffffffu, mt0, 1));
        mt0 = fmaxf(mt0, __shfl_xor_sync(0xffffffffu, mt0, 2));
        mt1 = fmaxf(mt1, __shfl_xor_sync(0xffffffffu, mt1, 1));
        mt1 = fmaxf(mt1, __shfl_xor_sync(0xffffffffu, mt1, 2));
        float mn0 = fmaxf(m0, mt0), mn1 = fmaxf(m1, mt1);
        float corr0 = __expf(m0 - mn0), corr1 = __expf(m1 - mn1);
        m0 = mn0; m1 = mn1;
        float b0l = mn0 * L2E, b1l = mn1 * L2E;

        unsigned p01[8], p23[8];
        __half2 acc0 = __floats2half2_rn(0.f, 0.f);
        __half2 acc1 = acc0;
        #pragma unroll
        for (int j = 0; j < 8; j++) {
            unsigned u01 = packh2(fmaf(s[j][0], L2E, -b0l), fmaf(s[j][1], L2E, -b0l));
            unsigned u23 = packh2(fmaf(s[j][2], L2E, -b1l), fmaf(s[j][3], L2E, -b1l));
            p01[j] = ex2h2(u01);
            p23[j] = ex2h2(u23);
            acc0 = __hadd2(acc0, *reinterpret_cast<__half2*>(&p01[j]));
            acc1 = __hadd2(acc1, *reinterpret_cast<__half2*>(&p23[j]));
        }
        float ls0 = __low2float(acc0) + __high2float(acc0);
        float ls1 = __low2float(acc1) + __high2float(acc1);
        ls0 += __shfl_xor_sync(0xffffffffu, ls0, 1);
        ls0 += __shfl_xor_sync(0xffffffffu, ls0, 2);
        ls1 += __shfl_xor_sync(0xffffffffu, ls1, 1);
        ls1 += __shfl_xor_sync(0xffffffffu, ls1, 2);
        l0 = l0 * corr0 + ls0;
        l1 = l1 * corr1 + ls1;
        #pragma unroll
        for (int j = 0; j < 8; j++) {
            oacc[j][0] *= corr0; oacc[j][1] *= corr0;
            oacc[j][2] *= corr1; oacc[j][3] *= corr1;
        }

        // O += P @ V  (P fragments = ex2 outputs; V via ldmatrix.x4)
        #pragma unroll
        for (int ks = 0; ks < 4; ks++) {
            const int kw = ks << 3;
            unsigned ap0 = p01[2*ks],     ap1 = p23[2*ks];
            unsigned ap2 = p01[2*ks + 1], ap3 = p23[2*ks + 1];
            #pragma unroll
            for (int p = 0; p < 4; p++) {
                unsigned bv[4];
                LDSM4(bv, vbb + ((((p << 4) + lr) * QST) + kw + lc) * 4);
                MMA_F16(oacc[2*p],     ap0, ap1, ap2, ap3, bv[0], bv[2]);
                MMA_F16(oacc[2*p + 1], ap0, ap1, ap2, ap3, bv[1], bv[3]);
            }
        }
    }

    const size_t obase = rbase * DIMX + (size_t)h * HD;
    float il0 = 1.0f / l0, il1 = 1.0f / l1;
    #pragma unroll
    for (int j = 0; j < 8; j++) {
        size_t o0 = obase + (size_t)(q0 + r0 + g) * DIMX + (j << 3) + (q4 << 1);
        size_t o1 = obase + (size_t)(q0 + r0 + 8 + g) * DIMX + (j << 3) + (q4 << 1);
        *reinterpret_cast<__half2*>(og + o0) =
            __floats2half2_rn(oacc[j][0] * il0, oacc[j][1] * il0);
        *reinterpret_cast<__half2*>(og + o1) =
            __floats2half2_rn(oacc[j][2] * il1, oacc[j][3] * il1);
    }
}

// ---------------- launch ------------------------------------------------------
extern "C" void kernel_launch(void* const* d_in, const int* in_sizes, int n_in,
                              void* d_out, int out_size)
{
    const float* x    = (const float*)d_in[0];
    const float* wq   = (const float*)d_in[2];
    const float* wk   = (const float*)d_in[3];
    const float* wv   = (const float*)d_in[4];
    const float* wo   = (const float*)d_in[5];
    const float* w_up = (const float*)d_in[6];
    const float* b_up = (const float*)d_in[7];
    const float* w_dn = (const float*)d_in[8];
    const float* b_dn = (const float*)d_in[9];
    const float* l1a  = (const float*)d_in[10];
    const float* l1b  = (const float*)d_in[11];
    const float* l2a  = (const float*)d_in[12];
    const float* l2b  = (const float*)d_in[13];
    float* out = (float*)d_out;

    __half *h, *qb, *kb, *vT, *attn, *ffh, *wt;
    float *x2;
    {
        void* p;
        cudaGetSymbolAddress(&p, g_h);    h    = (__half*)p;
        cudaGetSymbolAddress(&p, g_q);    qb   = (__half*)p;
        cudaGetSymbolAddress(&p, g_k);    kb   = (__half*)p;
        cudaGetSymbolAddress(&p, g_v);    vT   = (__half*)p;
        cudaGetSymbolAddress(&p, g_attn); attn = (__half*)p;
        cudaGetSymbolAddress(&p, g_x2);   x2   = (float*)p;
        cudaGetSymbolAddress(&p, g_ffh);  ffh  = (__half*)p;
        cudaGetSymbolAddress(&p, g_wt);   wt   = (__half*)p;
    }

    __half* wqkv_t = wt;
    __half* wo_t   = wt + 3 * 1024 * 1024;
    __half* wu_t   = wt + 4 * 1024 * 1024;
    __half* wd_t   = wt + 8 * 1024 * 1024;

    cudaFuncSetAttribute(gemm_fp16<4,false,false,false>, cudaFuncAttributeMaxDynamicSharedMemorySize, GEMM_SMEM);
    cudaFuncSetAttribute(gemm_fp16<0,false,false,true >, cudaFuncAttributeMaxDynamicSharedMemorySize, GEMM_SMEM);
    cudaFuncSetAttribute(gemm_fp16<2,true ,true ,false>, cudaFuncAttributeMaxDynamicSharedMemorySize, GEMM_SMEM);
    cudaFuncSetAttribute(gemm_fp16<0,true ,false,true >, cudaFuncAttributeMaxDynamicSharedMemorySize, GEMM_SMEM);
    cudaFuncSetAttribute(attn_tc, cudaFuncAttributeMaxDynamicSharedMemorySize, ATT_SMEM);

    dim3 thr(256);

    prep_all_T<<<12288, thr>>>(wq, wk, wv, wo, w_up, w_dn, wt);

    ln_kernel<<<MTOT, thr>>>(x, l1a, l1b, h);

    gemm_fp16<4,false,false,false><<<dim3(3072/128, MTOT/128), thr, GEMM_SMEM>>>(
        h, wqkv_t, nullptr, nullptr, nullptr, qb, kb, vT, MTOT, 3072, DIMX);

    attn_tc<<<dim3(SSQ/128, BB*NH), thr, ATT_SMEM>>>(qb, kb, vT, attn);

    gemm_fp16<0,false,false,true><<<dim3(DIMX/128, MTOT/128), thr, GEMM_SMEM>>>(
        attn, wo_t, nullptr, x, x2, nullptr, nullptr, nullptr, MTOT, DIMX, DIMX);

    ln_kernel<<<MTOT, thr>>>(x2, l2a, l2b, h);

    gemm_fp16<2,true,true,false><<<dim3(DFF/128, MTOT/128), thr, GEMM_SMEM>>>(
        h, wu_t, b_up, nullptr, nullptr, ffh, nullptr, nullptr, MTOT, DFF, DIMX);

    gemm_fp16<0,true,false,true><<<dim3(DIMX/128, MTOT/128), thr, GEMM_SMEM>>>(
        ffh, wd_t, b_dn, x2, out, nullptr, nullptr, nullptr, MTOT, DIMX, DFF);
}

// round 16
// speedup vs baseline: 1.8258x; 1.0046x over previous
#include <cuda_runtime.h>
#include <cuda_fp16.h>
#include <math.h>

#define DIMX 1024
#define NH   16
#define HD   64
#define DFF  4096
#define BB   2
#define SSQ  2048
#define MTOT (BB*SSQ)
#define EPSV 1e-6f

// ---------------- scratch (device globals) ----------------------------------
__device__ __align__(256) __half g_h   [MTOT*DIMX];
__device__ __align__(256) __half g_q   [MTOT*DIMX];
__device__ __align__(256) __half g_k   [MTOT*DIMX];
__device__ __align__(256) __half g_v   [MTOT*DIMX];   // vT [1024][MTOT]
__device__ __align__(256) __half g_attn[MTOT*DIMX];
__device__ __align__(256) float  g_x2  [MTOT*DIMX];
__device__ __align__(256) __half g_ffh [MTOT*DFF];
__device__ __align__(256) __half g_wt  [12*1024*1024];  // transposed fp16 weights

// ---------------- helpers ----------------------------------------------------
__device__ __forceinline__ void cp16(unsigned s, const void* g) {
    asm volatile("cp.async.cg.shared.global [%0], [%1], 16;" :: "r"(s), "l"(g));
}
#define CP_COMMIT() asm volatile("cp.async.commit_group;")
#define CP_WAIT(n)  asm volatile("cp.async.wait_group %0;" :: "n"(n))

#define MMA_F16(c, a0, a1, a2, a3, b0, b1) asm volatile( \
    "mma.sync.aligned.m16n8k16.row.col.f32.f16.f16.f32 " \
    "{%0,%1,%2,%3}, {%4,%5,%6,%7}, {%8,%9}, {%0,%1,%2,%3};" \
    : "+f"((c)[0]), "+f"((c)[1]), "+f"((c)[2]), "+f"((c)[3]) \
    : "r"(a0), "r"(a1), "r"(a2), "r"(a3), "r"(b0), "r"(b1))

#define LDSM4(r, a) asm volatile( \
    "ldmatrix.sync.aligned.m8n8.x4.shared.b16 {%0,%1,%2,%3}, [%4];" \
    : "=r"((r)[0]), "=r"((r)[1]), "=r"((r)[2]), "=r"((r)[3]) : "r"(a))

__device__ __forceinline__ unsigned packh2(float a, float b) {
    unsigned u;
    asm("cvt.rn.f16x2.f32 %0, %2, %1;" : "=r"(u) : "f"(a), "f"(b));
    return u;
}
__device__ __forceinline__ unsigned ex2h2(unsigned a) {
    unsigned u;
    asm("ex2.approx.f16x2 %0, %1;" : "=r"(u) : "r"(a));
    return u;
}

// ---------------- merged weight prep (single launch) --------------------------
__global__ void __launch_bounds__(256) prep_all_T(
    const float* __restrict__ wq, const float* __restrict__ wk,
    const float* __restrict__ wv, const float* __restrict__ wo,
    const float* __restrict__ wu, const float* __restrict__ wd,
    __half* __restrict__ wt)
{
    __shared__ float t[32][33];
    int bid = blockIdx.x;
    const float* w; __half* o; int K, N, tile;
    if      (bid < 1024) { w = wq; o = wt;                 K = 1024; N = 1024; tile = bid; }
    else if (bid < 2048) { w = wk; o = wt + 1*1024*1024;   K = 1024; N = 1024; tile = bid - 1024; }
    else if (bid < 3072) { w = wv; o = wt + 2*1024*1024;   K = 1024; N = 1024; tile = bid - 2048; }
    else if (bid < 4096) { w = wo; o = wt + 3*1024*1024;   K = 1024; N = 1024; tile = bid - 3072; }
    else if (bid < 8192) { w = wu; o = wt + 4*1024*1024;   K = 1024; N = 4096; tile = bid - 4096; }
    else                 { w = wd; o = wt + 8*1024*1024;   K = 4096; N = 1024; tile = bid - 8192; }
    int ntN = N >> 5;
    int nb = (tile % ntN) << 5;
    int kt = (tile / ntN) << 5;
    int tid = threadIdx.x;
    #pragma unroll
    for (int i = 0; i < 4; i++) {
        int idx = tid + (i << 8);
        int r = idx >> 5, c = idx & 31;
        t[r][c] = w[(size_t)(kt + r) * N + nb + c];
    }
    __syncthreads();
    #pragma unroll
    for (int i = 0; i < 4; i++) {
        int idx = tid + (i << 8);
        int r = idx >> 5, c = idx & 31;
        o[(size_t)(nb + r) * K + kt + c] = __float2half(t[c][r]);
    }
}

// ---------------- LayerNorm (emits fp16) --------------------------------------
__global__ void __launch_bounds__(256) ln_kernel(
    const float* __restrict__ x, const float* __restrict__ alpha,
    const float* __restrict__ beta, __half* __restrict__ y)
{
    int row = blockIdx.x;
    int t = threadIdx.x;
    const float4* xr = reinterpret_cast<const float4*>(x + (size_t)row * DIMX);
    float4 v = xr[t];
    float s  = v.x + v.y + v.z + v.w;
    float sq = v.x*v.x + v.y*v.y + v.z*v.z + v.w*v.w;
    #pragma unroll
    for (int o = 16; o; o >>= 1) {
        s  += __shfl_xor_sync(0xffffffffu, s,  o);
        sq += __shfl_xor_sync(0xffffffffu, sq, o);
    }
    __shared__ float ss[8], ssq[8];
    int w = t >> 5, l = t & 31;
    if (l == 0) { ss[w] = s; ssq[w] = sq; }
    __syncthreads();
    if (w == 0) {
        s  = (l < 8) ? ss[l]  : 0.f;
        sq = (l < 8) ? ssq[l] : 0.f;
        #pragma unroll
        for (int o = 4; o; o >>= 1) {
            s  += __shfl_xor_sync(0xffffffffu, s,  o);
            sq += __shfl_xor_sync(0xffffffffu, sq, o);
        }
        if (l == 0) { ss[0] = s; ssq[0] = sq; }
    }
    __syncthreads();
    s = ss[0]; sq = ssq[0];
    float mu  = s * (1.0f / DIMX);
    float var = (sq - (float)DIMX * mu * mu) * (1.0f / (DIMX - 1));
    float sig = sqrtf(fmaxf(var, 0.f));
    float inv = 1.0f / (sig + EPSV);
    float4 a = reinterpret_cast<const float4*>(alpha)[t];
    float4 b = reinterpret_cast<const float4*>(beta)[t];
    __half2 h0 = __floats2half2_rn(a.x * (v.x - mu) * inv + b.x,
                                   a.y * (v.y - mu) * inv + b.y);
    __half2 h1 = __floats2half2_rn(a.z * (v.z - mu) * inv + b.z,
                                   a.w * (v.w - mu) * inv + b.w);
    size_t off = (size_t)row * DIMX + t * 4;
    reinterpret_cast<__half2*>(y + off)[0] = h0;
    reinterpret_cast<__half2*>(y + off)[1] = h1;
}

// ---------------- FP16 tensor GEMM (m16n8k16, ldmatrix fragments) -------------
// OM: 0 = fp32 out (+res), 2 = fp16 rows, 4 = fused QKV (q scaled 1/8, k rows,
// v transposed).
#define STAGES 4
#define PW 20
#define STAGE_U32 (256*PW)
#define GEMM_SMEM (STAGES * STAGE_U32 * 4)

template<int OM, bool BIAS, bool RELU, bool RES>
__global__ void __launch_bounds__(256, 2) gemm_fp16(
    const __half* __restrict__ A, const __half* __restrict__ Bt,
    const float* __restrict__ bias, const float* __restrict__ res,
    float* __restrict__ C, __half* __restrict__ Ch,
    __half* __restrict__ Ch2, __half* __restrict__ Ch3,
    int M, int N, int K)
{
    extern __shared__ unsigned smg[];
    const int tid  = threadIdx.x;
    const int bm   = blockIdx.y * 128, bn = blockIdx.x * 128;
    const int warp = tid >> 5, lane = tid & 31;
    const int wm   = (warp >> 2) << 6;
    const int wn   = (warp & 3) << 5;
    const int g    = lane >> 2, q = lane & 3;
    const int lr   = (lane & 7) + ((lane >> 3) & 1) * 8;
    const int lc   = (lane >> 4) * 4;

    const unsigned sbase = (unsigned)__cvta_generic_to_shared(smg);

    float acc[4][4][4];
    #pragma unroll
    for (int mi = 0; mi < 4; mi++)
        #pragma unroll
        for (int nj = 0; nj < 4; nj++)
            #pragma unroll
            for (int e = 0; e < 4; e++) acc[mi][nj][e] = 0.f;

    const int nt = K >> 5;

    #define G_ISSUE(buf, kt) do { \
        unsigned ab_ = sbase + (buf) * (STAGE_U32 * 4); \
        unsigned bb_ = ab_ + 128 * PW * 4; \
        _Pragma("unroll") \
        for (int i_ = 0; i_ < 2; i_++) { \
            int idx_ = tid + (i_ << 8); \
            int row_ = idx_ >> 2, seg_ = idx_ & 3; \
            cp16(ab_ + (row_ * PW + seg_ * 4) * 4, \
                 A  + (size_t)(bm + row_) * K + (kt) * 32 + seg_ * 8); \
            cp16(bb_ + (row_ * PW + seg_ * 4) * 4, \
                 Bt + (size_t)(bn + row_) * K + (kt) * 32 + seg_ * 8); \
        } \
    } while (0)

    #pragma unroll
    for (int s = 0; s < STAGES - 1; s++) {
        if (s < nt) G_ISSUE(s, s);
        CP_COMMIT();
    }

    for (int kt = 0; kt < nt; kt++) {
        CP_WAIT(STAGES - 2);
        __syncthreads();
        int nl = kt + STAGES - 1;
        if (nl < nt) G_ISSUE(nl % STAGES, nl);
        CP_COMMIT();

        const unsigned ab = sbase + (kt % STAGES) * (STAGE_U32 * 4);
        const unsigned bb = ab + 128 * PW * 4;
        #pragma unroll
        for (int ks = 0; ks < 2; ks++) {
            const int kw = ks << 3;
            unsigned af[4][4], bp[2][4];
            #pragma unroll
            for (int mi = 0; mi < 4; mi++)
                LDSM4(af[mi], ab + (((wm + (mi << 4) + lr) * PW) + kw + lc) * 4);
            #pragma unroll
            for (int p = 0; p < 2; p++)
                LDSM4(bp[p], bb + (((wn + (p << 4) + lr) * PW) + kw + lc) * 4);
            #pragma unroll
            for (int mi = 0; mi < 4; mi++)
                #pragma unroll
                for (int nj = 0; nj < 4; nj++)
                    MMA_F16(acc[mi][nj], af[mi][0], af[mi][1], af[mi][2], af[mi][3],
                            bp[nj >> 1][nj & 1], bp[nj >> 1][2 + (nj & 1)]);
        }
    }

    // epilogue
    #pragma unroll
    for (int mi = 0; mi < 4; mi++) {
        int r = bm + wm + (mi << 4) + g;
        #pragma unroll
        for (int nj = 0; nj < 4; nj++) {
            int c = bn + wn + (nj << 3) + (q << 1);
            float2 v0, v1;
            v0.x = acc[mi][nj][0]; v0.y = acc[mi][nj][1];
            v1.x = acc[mi][nj][2]; v1.y = acc[mi][nj][3];
            if (BIAS) {
                float2 bv = *reinterpret_cast<const float2*>(bias + c);
                v0.x += bv.x; v0.y += bv.y; v1.x += bv.x; v1.y += bv.y;
            }
            if (RELU) {
                v0.x = fmaxf(v0.x, 0.f); v0.y = fmaxf(v0.y, 0.f);
                v1.x = fmaxf(v1.x, 0.f); v1.y = fmaxf(v1.y, 0.f);
            }
            if (RES) {
                float2 r0 = *reinterpret_cast<const float2*>(res + (size_t)r * N + c);
                float2 r1 = *reinterpret_cast<const float2*>(res + (size_t)(r + 8) * N + c);
                v0.x += r0.x; v0.y += r0.y; v1.x += r1.x; v1.y += r1.y;
            }
            if (OM == 0) {
                *reinterpret_cast<float2*>(C + (size_t)r * N + c) = v0;
                *reinterpret_cast<float2*>(C + (size_t)(r + 8) * N + c) = v1;
            } else if (OM == 2) {
                *reinterpret_cast<__half2*>(Ch + (size_t)r * N + c) = __floats2half2_rn(v0.x, v0.y);
                *reinterpret_cast<__half2*>(Ch + (size_t)(r + 8) * N + c) = __floats2half2_rn(v1.x, v1.y);
            } else {  // OM == 4: fused QKV
                if (bn < 1024) {
                    *reinterpret_cast<__half2*>(Ch + (size_t)r * DIMX + c) =
                        __floats2half2_rn(v0.x * 0.125f, v0.y * 0.125f);
                    *reinterpret_cast<__half2*>(Ch + (size_t)(r + 8) * DIMX + c) =
                        __floats2half2_rn(v1.x * 0.125f, v1.y * 0.125f);
                } else if (bn < 2048) {
                    int ck = c - 1024;
                    *reinterpret_cast<__half2*>(Ch2 + (size_t)r * DIMX + ck) = __floats2half2_rn(v0.x, v0.y);
                    *reinterpret_cast<__half2*>(Ch2 + (size_t)(r + 8) * DIMX + ck) = __floats2half2_rn(v1.x, v1.y);
                } else {
                    int cv = c - 2048;
                    Ch3[(size_t)cv * M + r]           = __float2half(v0.x);
                    Ch3[(size_t)(cv + 1) * M + r]     = __float2half(v0.y);
                    Ch3[(size_t)cv * M + r + 8]       = __float2half(v1.x);
                    Ch3[(size_t)(cv + 1) * M + r + 8] = __float2half(v1.y);
                }
            }
        }
    }
}

// ---------------- FP16 flash attention (unchanged from round 15) --------------
#define QST 36
#define ATT_SMEM ((128*QST + 2*64*QST + 2*64*QST) * 4)

__global__ void __launch_bounds__(256, 2) attn_tc(
    const __half* __restrict__ qb, const __half* __restrict__ kb,
    const __half* __restrict__ vT, __half* __restrict__ og)
{
    extern __shared__ unsigned sma[];
    unsigned* Qs = sma;

    const int tid  = threadIdx.x;
    const int warp = tid >> 5, lane = tid & 31;
    const int g    = lane >> 2, q4 = lane & 3;
    const int lr   = (lane & 7) + ((lane >> 3) & 1) * 8;
    const int lc   = (lane >> 4) * 4;
    const int bh   = blockIdx.y;
    const int b    = bh >> 4, h = bh & 15;
    const int q0   = blockIdx.x * 128;
    const size_t rbase = (size_t)b * SSQ;
    const int r0 = warp << 4;
    const unsigned sbase = (unsigned)__cvta_generic_to_shared(sma);
    const unsigned ksb = sbase + 128 * QST * 4;
    const unsigned vsb = ksb + 2 * 64 * QST * 4;

    #pragma unroll
    for (int i = 0; i < 4; i++) {
        int f = tid + (i << 8);
        int row = f >> 3, seg = f & 7;
        cp16(sbase + (row * QST + seg * 4) * 4,
             qb + ((rbase + q0 + row) << 10) + (h << 6) + (seg << 3));
    }
    CP_COMMIT();

    #define A_ISSUE(buf, kt) do { \
        _Pragma("unroll") \
        for (int i_ = 0; i_ < 2; i_++) { \
            int f_ = tid + (i_ << 8); \
            int rr_ = f_ >> 3, sg_ = f_ & 7; \
            cp16(ksb + ((buf) * 64 * QST + rr_ * QST + sg_ * 4) * 4, \
                 kb + ((rbase + (kt) + rr_) << 10) + (h << 6) + (sg_ << 3)); \
            cp16(vsb + ((buf) * 64 * QST + rr_ * QST + sg_ * 4) * 4, \
                 vT + (size_t)((h << 6) + rr_) * MTOT + rbase + (kt) + (sg_ << 3)); \
        } \
    } while (0)

    CP_WAIT(0);
    __syncthreads();
    unsigned aq[4][4];
    #pragma unroll
    for (int ks = 0; ks < 4; ks++) {
        aq[ks][0] = Qs[(r0 + g) * QST + (ks << 3) + q4];
        aq[ks][1] = Qs[(r0 + 8 + g) * QST + (ks << 3) + q4];
        aq[ks][2] = Qs[(r0 + g) * QST + (ks << 3) + q4 + 4];
        aq[ks][3] = Qs[(r0 + 8 + g) * QST + (ks << 3) + q4 + 4];
    }

    A_ISSUE(0, 0);
    CP_COMMIT();

    float m0 = -1e30f, m1 = -1e30f, l0 = 0.f, l1 = 0.f;
    float oacc[8][4];
    #pragma unroll
    for (int j = 0; j < 8; j++)
        #pragma unroll
        for (int e = 0; e < 4; e++) oacc[j][e] = 0.f;

    const float L2E = 1.4426950408889634f;
    const int NKT = SSQ / 64;
    for (int t = 0; t < NKT; t++) {
        __syncthreads();
        if (t + 1 < NKT) A_ISSUE((t + 1) & 1, (t + 1) * 64);
        CP_COMMIT();
        CP_WAIT(1);
        __syncthreads();

        const unsigned kbb = ksb + (t & 1) * 64 * QST * 4;
        const unsigned vbb = vsb + (t & 1) * 64 * QST * 4;

        float s[8][4];
        #pragma unroll
        for (int j = 0; j < 8; j++)
            #pragma unroll
            for (int e = 0; e < 4; e++) s[j][e] = 0.f;
        #pragma unroll
        for (int ks = 0; ks < 4; ks++) {
            const int kw = ks << 3;
            #pragma unroll
            for (int p = 0; p < 4; p++) {
                unsigned bk[4];
                LDSM4(bk, kbb + ((((p << 4) + lr) * QST) + kw + lc) * 4);
                MMA_F16(s[2*p],     aq[ks][0], aq[ks][1], aq[ks][2], aq[ks][3], bk[0], bk[2]);
                MMA_F16(s[2*p + 1], aq[ks][0], aq[ks][1], aq[ks][2], aq[ks][3], bk[1], bk[3]);
            }
        }

        float mt0 = -1e30f, mt1 = -1e30f;
        #pragma unroll
        for (int j = 0; j < 8; j++) {
            mt0 = fmaxf(mt0, fmaxf(s[j][0], s[j][1]));
            mt1 = fmaxf(mt1, fmaxf(s[j][2], s[j][3]));
        }
        mt0 = fmaxf(mt0, __shfl_xor_sync(0xffffffffu, mt0, 1));
        mt0 = fmaxf(mt0, __shfl_xor_sync(0xffffffffu, mt0, 2));
        mt1 = fmaxf(mt1, __shfl_xor_sync(0xffffffffu, mt1, 1));
        mt1 = fmaxf(mt1, __shfl_xor_sync(0xffffffffu, mt1, 2));
        float mn0 = fmaxf(m0, mt0), mn1 = fmaxf(m1, mt1);
        float corr0 = __expf(m0 - mn0), corr1 = __expf(m1 - mn1);
        m0 = mn0; m1 = mn1;
        float b0l = mn0 * L2E, b1l = mn1 * L2E;

        unsigned p01[8], p23[8];
        __half2 acc0 = __floats2half2_rn(0.f, 0.f);
        __half2 acc1 = acc0;
        #pragma unroll
        for (int j = 0; j < 8; j++) {
            unsigned u01 = packh2(fmaf(s[j][0], L2E, -b0l), fmaf(s[j][1], L2E, -b0l));
            unsigned u23 = packh2(fmaf(s[j][2], L2E, -b1l), fmaf(s[j][3], L2E, -b1l));
            p01[j] = ex2h2(u01);
            p23[j] = ex2h2(u23);
            acc0 = __hadd2(acc0, *reinterpret_cast<__half2*>(&p01[j]));
            acc1 = __hadd2(acc1, *reinterpret_cast<__half2*>(&p23[j]));
        }
        float ls0 = __low2float(acc0) + __high2float(acc0);
        float ls1 = __low2float(acc1) + __high2float(acc1);
        ls0 += __shfl_xor_sync(0xffffffffu, ls0, 1);
        ls0 += __shfl_xor_sync(0xffffffffu, ls0, 2);
        ls1 += __shfl_xor_sync(0xffffffffu, ls1, 1);
        ls1 += __shfl_xor_sync(0xffffffffu, ls1, 2);
        l0 = l0 * corr0 + ls0;
        l1 = l1 * corr1 + ls1;
        #pragma unroll
        for (int j = 0; j < 8; j++) {
            oacc[j][0] *= corr0; oacc[j][1] *= corr0;
            oacc[j][2] *= corr1; oacc[j][3] *= corr1;
        }

        #pragma unroll
        for (int ks = 0; ks < 4; ks++) {
            const int kw = ks << 3;
            unsigned ap0 = p01[2*ks],     ap1 = p23[2*ks];
            unsigned ap2 = p01[2*ks + 1], ap3 = p23[2*ks + 1];
            #pragma unroll
            for (int p = 0; p < 4; p++) {
                unsigned bv[4];
                LDSM4(bv, vbb + ((((p << 4) + lr) * QST) + kw + lc) * 4);
                MMA_F16(oacc[2*p],     ap0, ap1, ap2, ap3, bv[0], bv[2]);
                MMA_F16(oacc[2*p + 1], ap0, ap1, ap2, ap3, bv[1], bv[3]);
            }
        }
    }

    const size_t obase = rbase * DIMX + (size_t)h * HD;
    float il0 = 1.0f / l0, il1 = 1.0f / l1;
    #pragma unroll
    for (int j = 0; j < 8; j++) {
        size_t o0 = obase + (size_t)(q0 + r0 + g) * DIMX + (j << 3) + (q4 << 1);
        size_t o1 = obase + (size_t)(q0 + r0 + 8 + g) * DIMX + (j << 3) + (q4 << 1);
        *reinterpret_cast<__half2*>(og + o0) =
            __floats2half2_rn(oacc[j][0] * il0, oacc[j][1] * il0);
        *reinterpret_cast<__half2*>(og + o1) =
            __floats2half2_rn(oacc[j][2] * il1, oacc[j][3] * il1);
    }
}

// ---------------- launch ------------------------------------------------------
extern "C" void kernel_launch(void* const* d_in, const int* in_sizes, int n_in,
                              void* d_out, int out_size)
{
    const float* x    = (const float*)d_in[0];
    const float* wq   = (const float*)d_in[2];
    const float* wk   = (const float*)d_in[3];
    const float* wv   = (const float*)d_in[4];
    const float* wo   = (const float*)d_in[5];
    const float* w_up = (const float*)d_in[6];
    const float* b_up = (const float*)d_in[7];
    const float* w_dn = (const float*)d_in[8];
    const float* b_dn = (const float*)d_in[9];
    const float* l1a  = (const float*)d_in[10];
    const float* l1b  = (const float*)d_in[11];
    const float* l2a  = (const float*)d_in[12];
    const float* l2b  = (const float*)d_in[13];
    float* out = (float*)d_out;

    __half *h, *qb, *kb, *vT, *attn, *ffh, *wt;
    float *x2;
    {
        void* p;
        cudaGetSymbolAddress(&p, g_h);    h    = (__half*)p;
        cudaGetSymbolAddress(&p, g_q);    qb   = (__half*)p;
        cudaGetSymbolAddress(&p, g_k);    kb   = (__half*)p;
        cudaGetSymbolAddress(&p, g_v);    vT   = (__half*)p;
        cudaGetSymbolAddress(&p, g_attn); attn = (__half*)p;
        cudaGetSymbolAddress(&p, g_x2);   x2   = (float*)p;
        cudaGetSymbolAddress(&p, g_ffh);  ffh  = (__half*)p;
        cudaGetSymbolAddress(&p, g_wt);   wt   = (__half*)p;
    }

    __half* wqkv_t = wt;
    __half* wo_t   = wt + 3 * 1024 * 1024;
    __half* wu_t   = wt + 4 * 1024 * 1024;
    __half* wd_t   = wt + 8 * 1024 * 1024;

    cudaFuncSetAttribute(gemm_fp16<4,false,false,false>, cudaFuncAttributeMaxDynamicSharedMemorySize, GEMM_SMEM);
    cudaFuncSetAttribute(gemm_fp16<0,false,false,true >, cudaFuncAttributeMaxDynamicSharedMemorySize, GEMM_SMEM);
    cudaFuncSetAttribute(gemm_fp16<2,true ,true ,false>, cudaFuncAttributeMaxDynamicSharedMemorySize, GEMM_SMEM);
    cudaFuncSetAttribute(gemm_fp16<0,true ,false,true >, cudaFuncAttributeMaxDynamicSharedMemorySize, GEMM_SMEM);
    cudaFuncSetAttribute(attn_tc, cudaFuncAttributeMaxDynamicSharedMemorySize, ATT_SMEM);

    dim3 thr(256);

    prep_all_T<<<12288, thr>>>(wq, wk, wv, wo, w_up, w_dn, wt);

    ln_kernel<<<MTOT, thr>>>(x, l1a, l1b, h);

    gemm_fp16<4,false,false,false><<<dim3(3072/128, MTOT/128), thr, GEMM_SMEM>>>(
        h, wqkv_t, nullptr, nullptr, nullptr, qb, kb, vT, MTOT, 3072, DIMX);

    attn_tc<<<dim3(SSQ/128, BB*NH), thr, ATT_SMEM>>>(qb, kb, vT, attn);

    gemm_fp16<0,false,false,true><<<dim3(DIMX/128, MTOT/128), thr, GEMM_SMEM>>>(
        attn, wo_t, nullptr, x, x2, nullptr, nullptr, nullptr, MTOT, DIMX, DIMX);

    ln_kernel<<<MTOT, thr>>>(x2, l2a, l2b, h);

    gemm_fp16<2,true,true,false><<<dim3(DFF/128, MTOT/128), thr, GEMM_SMEM>>>(
        h, wu_t, b_up, nullptr, nullptr, ffh, nullptr, nullptr, MTOT, DFF, DIMX);

    gemm_fp16<0,true,false,true><<<dim3(DIMX/128, MTOT/128), thr, GEMM_SMEM>>>(
        ffh, wd_t, b_dn, x2, out, nullptr, nullptr, nullptr, MTOT, DIMX, DFF);
}